// round 6
// baseline (speedup 1.0000x reference)
#include <cuda_runtime.h>
#include <cstddef>

#define NB   8
#define NRQ  300
#define DIM  256
#define NHD  8
#define HDM  32
#define SS   49
#define DDI  64
#define FFD  2048
#define NCLS 80
#define ROWS 2400   // NB*NRQ

// ------------------------- scratch (device globals) -------------------------
__device__ float g_qk   [ROWS * DIM];
__device__ float g_qkp  [ROWS * 512];                 // q proj | k proj
__device__ float g_vp   [ROWS * DIM];
__device__ float g_mflag[NB * NRQ * NRQ];             // 1 = masked
__device__ float g_scores[(size_t)NB * NHD * NRQ * NRQ];
__device__ float g_ctx  [ROWS * DIM];
__device__ float g_tgt2 [ROWS * DIM];
__device__ float g_pf1  [ROWS * DIM];
__device__ float g_params[(size_t)ROWS * 2 * DIM * DDI];   // 314 MB
__device__ float g_f2   [(size_t)ROWS * SS * DIM];         // 120 MB
__device__ float g_dynraw[ROWS * DIM];
__device__ float g_pf2  [ROWS * DIM];
__device__ float g_pfB  [ROWS * DIM];
__device__ float g_ffh  [(size_t)ROWS * FFD];
__device__ float g_t2   [ROWS * DIM];
__device__ float g_fc   [ROWS * DIM];
__device__ float g_g1   [ROWS * DIM];
__device__ float g_clsf [ROWS * DIM];

static inline int cdiv(int a, int b) { return (a + b - 1) / b; }

// ------------------------- generic SGEMM: C = A*B^T + bias -------------------
// A [M,K] row-major, B [N,K] row-major (torch Linear weight), K % 16 == 0.
__global__ __launch_bounds__(256) void sgemm_bias(
    const float* __restrict__ A, const float* __restrict__ B,
    const float* __restrict__ bias, float* __restrict__ C,
    int M, int N, int K, int relu)
{
    __shared__ float As[16][132];
    __shared__ float Bs[16][132];
    int tid = threadIdx.x;
    int bm = blockIdx.y * 128, bn = blockIdx.x * 128;
    int ty = tid >> 4, tx = tid & 15;
    float acc[8][8];
#pragma unroll
    for (int i = 0; i < 8; i++)
#pragma unroll
        for (int j = 0; j < 8; j++) acc[i][j] = 0.f;

    int lm  = tid >> 1;         // 0..127 row within tile
    int lk0 = (tid & 1) * 8;    // 0 or 8

    for (int k0 = 0; k0 < K; k0 += 16) {
#pragma unroll
        for (int i = 0; i < 8; i++) {
            int k = lk0 + i;
            int gr = bm + lm;
            As[k][lm] = (gr < M) ? A[(size_t)gr * K + k0 + k] : 0.f;
            int gn = bn + lm;
            Bs[k][lm] = (gn < N) ? B[(size_t)gn * K + k0 + k] : 0.f;
        }
        __syncthreads();
#pragma unroll
        for (int k = 0; k < 16; k++) {
            float a[8], b[8];
#pragma unroll
            for (int i = 0; i < 8; i++) a[i] = As[k][ty * 8 + i];
#pragma unroll
            for (int j = 0; j < 8; j++) b[j] = Bs[k][tx * 8 + j];
#pragma unroll
            for (int i = 0; i < 8; i++)
#pragma unroll
                for (int j = 0; j < 8; j++) acc[i][j] = fmaf(a[i], b[j], acc[i][j]);
        }
        __syncthreads();
    }
#pragma unroll
    for (int i = 0; i < 8; i++) {
        int gr = bm + ty * 8 + i;
        if (gr >= M) continue;
#pragma unroll
        for (int j = 0; j < 8; j++) {
            int gc = bn + tx * 8 + j;
            if (gc >= N) continue;
            float v = acc[i][j];
            if (bias) v += bias[gc];
            if (relu) v = fmaxf(v, 0.f);
            C[(size_t)gr * N + gc] = v;
        }
    }
}

// ------------------------- IoU relation mask --------------------------------
__global__ void iou_mask_kernel(const float* __restrict__ bboxes,
                                const float* __restrict__ mask)
{
    int idx = blockIdx.x * blockDim.x + threadIdx.x;
    if (idx >= NB * NRQ * NRQ) return;
    int j = idx % NRQ;
    int i = (idx / NRQ) % NRQ;
    int n = idx / (NRQ * NRQ);
    const float* bi = bboxes + (size_t)(n * NRQ + i) * 4;
    const float* bj = bboxes + (size_t)(n * NRQ + j) * 4;
    float ax0 = bi[0], ay0 = bi[1], ax1 = bi[2], ay1 = bi[3];
    float bx0 = bj[0], by0 = bj[1], bx1 = bj[2], by1 = bj[3];
    float areaA = (ax1 - ax0) * (ay1 - ay0);
    float areaB = (bx1 - bx0) * (by1 - by0);
    float lx = fmaxf(ax0, bx0), ly = fmaxf(ay0, by0);
    float rx = fminf(ax1, bx1), ry = fminf(ay1, by1);
    float w = fmaxf(rx - lx, 0.f), h = fmaxf(ry - ly, 0.f);
    float inter = w * h;
    float uni = areaA + areaB - inter;
    float iou = inter / fmaxf(uni, 1e-9f);
    float mi = mask[n * NRQ + i], mj = mask[n * NRQ + j];
    bool masked = ((iou < 0.5f) && mi > 0.f && mj > 0.f) || (i == j && mi == 0.f);
    g_mflag[idx] = masked ? 1.f : 0.f;
}

// ------------------------- qk = pro + query ---------------------------------
__global__ void qkadd_kernel(const float* __restrict__ pro, const float* __restrict__ query)
{
    int idx = blockIdx.x * blockDim.x + threadIdx.x;
    if (idx >= ROWS * DIM) return;
    g_qk[idx] = pro[idx] + query[idx];
}

// ------------------------- attention scores ---------------------------------
// grid (10, NHD, NB), block 256: scores[n,h,q,k] = (Q.K)/sqrt(32), masked select
__global__ void scores_kernel()
{
    int n = blockIdx.z, h = blockIdx.y, qt = blockIdx.x * 32;
    __shared__ float Qs[32][32];
    __shared__ float Ks[32][33];
    int tid = threadIdx.x;
    int r = tid / 32, c = tid % 32;
    for (int rr = r; rr < 32; rr += 8) {
        int q = qt + rr;
        Qs[rr][c] = (q < NRQ) ? g_qkp[(size_t)(n * NRQ + q) * 512 + h * 32 + c] : 0.f;
    }
    const float scale = 0.17677669529663687f;  // 1/sqrt(32)
    for (int kt = 0; kt < NRQ; kt += 32) {
        __syncthreads();
        for (int rr = r; rr < 32; rr += 8) {
            int k = kt + rr;
            Ks[rr][c] = (k < NRQ) ? g_qkp[(size_t)(n * NRQ + k) * 512 + 256 + h * 32 + c] : 0.f;
        }
        __syncthreads();
        int kk = tid % 32, qr0 = tid / 32;
        float acc[4] = {0.f, 0.f, 0.f, 0.f};
#pragma unroll
        for (int d = 0; d < 32; d++) {
            float kv = Ks[kk][d];
#pragma unroll
            for (int u = 0; u < 4; u++) acc[u] += Qs[qr0 + u * 8][d] * kv;
        }
#pragma unroll
        for (int u = 0; u < 4; u++) {
            int q = qt + qr0 + u * 8;
            int k = kt + kk;
            if (q < NRQ && k < NRQ) {
                float flag = g_mflag[(size_t)(n * NRQ + q) * NRQ + k];
                size_t off = ((size_t)(n * NHD + h) * NRQ + q) * NRQ + k;
                g_scores[off] = (flag > 0.f) ? -1e9f : acc[u] * scale;
            }
        }
    }
}

// ------------------------- row softmax (one warp per row) -------------------
__global__ void softmax_kernel()
{
    int row = blockIdx.x * 8 + threadIdx.x / 32;
    int lane = threadIdx.x % 32;
    if (row >= NB * NHD * NRQ) return;
    float* p = g_scores + (size_t)row * NRQ;
    float mx = -1e30f;
    for (int k = lane; k < NRQ; k += 32) mx = fmaxf(mx, p[k]);
    for (int o = 16; o; o >>= 1) mx = fmaxf(mx, __shfl_xor_sync(0xffffffffu, mx, o));
    float sum = 0.f;
    for (int k = lane; k < NRQ; k += 32) { float e = __expf(p[k] - mx); p[k] = e; sum += e; }
    for (int o = 16; o; o >>= 1) sum += __shfl_xor_sync(0xffffffffu, sum, o);
    float inv = 1.f / sum;
    for (int k = lane; k < NRQ; k += 32) p[k] *= inv;
}

// ------------------------- ctx = attn @ V -----------------------------------
__global__ void ctx_kernel()
{
    int idx = blockIdx.x * blockDim.x + threadIdx.x;
    if (idx >= ROWS * DIM) return;
    int col = idx & 255;
    int row = idx >> 8;             // n*NRQ + q
    int n = row / NRQ, q = row % NRQ;
    int h = col >> 5;
    const float* ap = g_scores + ((size_t)(n * NHD + h) * NRQ + q) * NRQ;
    float acc = 0.f;
    for (int k = 0; k < NRQ; k++)
        acc += ap[k] * g_vp[(size_t)(n * NRQ + k) * DIM + col];
    g_ctx[idx] = acc;
}

// ------------------------- LayerNorm rows of 256 ----------------------------
// out = ln(x [+ res]) [relu] [* mask[row]]
__global__ void ln_kernel(const float* __restrict__ x, const float* __restrict__ res,
                          const float* __restrict__ mask, float* __restrict__ out, int relu)
{
    int row = blockIdx.x;
    int c = threadIdx.x;
    size_t base = (size_t)row * DIM;
    float v = x[base + c];
    if (res) v += res[base + c];
    float s = v, q = v * v;
    for (int o = 16; o; o >>= 1) {
        s += __shfl_xor_sync(0xffffffffu, s, o);
        q += __shfl_xor_sync(0xffffffffu, q, o);
    }
    __shared__ float ss[8], sq[8];
    int w = c >> 5, lane = c & 31;
    if (lane == 0) { ss[w] = s; sq[w] = q; }
    __syncthreads();
    float tot = 0.f, totq = 0.f;
#pragma unroll
    for (int i = 0; i < 8; i++) { tot += ss[i]; totq += sq[i]; }
    float mean = tot * (1.f / DIM);
    float var = totq * (1.f / DIM) - mean * mean;
    float y = (v - mean) * rsqrtf(var + 1e-5f);
    if (relu) y = fmaxf(y, 0.f);
    if (mask) y *= mask[row];
    out[base + c] = y;
}

// ------------------------- DynamicConv per instance -------------------------
// One CTA per instance n. smem: feats[49][256] | p[64*256] | f1[49][64]
__global__ __launch_bounds__(256) void dynconv_kernel(const float* __restrict__ roi)
{
    extern __shared__ float sm[];
    float* fsm  = sm;                 // 12544
    float* psm  = sm + 12544;         // 16384
    float* f1sm = psm + 16384;        // 3136
    int n = blockIdx.x, tid = threadIdx.x;

    for (int i = tid; i < SS * DIM; i += 256) {
        int s = i >> 8, d = i & 255;
        fsm[i] = roi[((size_t)s * ROWS + n) * DIM + d];
    }
    const float* pr = g_params + (size_t)n * (2 * DIM * DDI);
    for (int i = tid; i < DIM * DDI; i += 256) psm[i] = pr[i];
    __syncthreads();

    // f1[s][e] = sum_d feats[s][d] * p1[d][e]
    int e = tid & 63, sb = tid >> 6;
    for (int s = sb; s < SS; s += 4) {
        float acc = 0.f;
        const float* fr = fsm + s * DIM;
#pragma unroll 8
        for (int d = 0; d < DIM; d++) acc += fr[d] * psm[d * DDI + e];
        f1sm[s * DDI + e] = acc;
    }
    __syncthreads();

    // ln over 64 + relu (one warp per row)
    int wid = tid >> 5, lane = tid & 31;
    for (int s = wid; s < SS; s += 8) {
        float a = f1sm[s * DDI + lane], b = f1sm[s * DDI + 32 + lane];
        float sum = a + b, ssq = a * a + b * b;
        for (int o = 16; o; o >>= 1) {
            sum += __shfl_xor_sync(0xffffffffu, sum, o);
            ssq += __shfl_xor_sync(0xffffffffu, ssq, o);
        }
        float mean = sum * (1.f / 64.f);
        float var = ssq * (1.f / 64.f) - mean * mean;
        float inv = rsqrtf(var + 1e-5f);
        f1sm[s * DDI + lane]      = fmaxf((a - mean) * inv, 0.f);
        f1sm[s * DDI + 32 + lane] = fmaxf((b - mean) * inv, 0.f);
    }
    // load p2 (distinct smem region from f1sm; f1 compute done)
    for (int i = tid; i < DIM * DDI; i += 256) psm[i] = pr[DIM * DDI + i];
    __syncthreads();

    // f2[s][d] = sum_e f1[s][e] * p2[e][d]  (thread = d, overwrite fsm)
    for (int s = 0; s < SS; s++) {
        float acc = 0.f;
#pragma unroll 8
        for (int ee = 0; ee < DDI; ee++) acc += f1sm[s * DDI + ee] * psm[ee * DIM + tid];
        fsm[s * DIM + tid] = acc;
    }
    __syncthreads();

    // ln over 256 + relu, write to g_f2
    for (int s = wid; s < SS; s += 8) {
        float vals[8];
        float sum = 0.f, ssq = 0.f;
#pragma unroll
        for (int u = 0; u < 8; u++) {
            float v = fsm[s * DIM + lane + u * 32];
            vals[u] = v; sum += v; ssq += v * v;
        }
        for (int o = 16; o; o >>= 1) {
            sum += __shfl_xor_sync(0xffffffffu, sum, o);
            ssq += __shfl_xor_sync(0xffffffffu, ssq, o);
        }
        float mean = sum * (1.f / DIM);
        float var = ssq * (1.f / DIM) - mean * mean;
        float inv = rsqrtf(var + 1e-5f);
#pragma unroll
        for (int u = 0; u < 8; u++) {
            float y = fmaxf((vals[u] - mean) * inv, 0.f);
            g_f2[(size_t)n * (SS * DIM) + s * DIM + lane + u * 32] = y;
        }
    }
}

// ------------------------- host launch --------------------------------------
template <typename T>
static float* sym(T& s) { void* p = nullptr; cudaGetSymbolAddress(&p, s); return (float*)p; }

extern "C" void kernel_launch(void* const* d_in, const int* in_sizes, int n_in,
                              void* d_out, int out_size)
{
    const float* bboxes   = (const float*)d_in[0];
    const float* pro      = (const float*)d_in[1];
    const float* roi      = (const float*)d_in[2];
    const float* query    = (const float*)d_in[3];
    const float* mask     = (const float*)d_in[4];
    const float* w_qkv    = (const float*)d_in[5];
    const float* b_qkv    = (const float*)d_in[6];
    const float* w_attn   = (const float*)d_in[7];
    const float* b_attn   = (const float*)d_in[8];
    const float* w_dyn    = (const float*)d_in[9];
    const float* b_dyn    = (const float*)d_in[10];
    const float* w_dyno   = (const float*)d_in[11];
    const float* b_dyno   = (const float*)d_in[12];
    const float* w_ff1    = (const float*)d_in[13];
    const float* b_ff1    = (const float*)d_in[14];
    const float* w_ff2    = (const float*)d_in[15];
    const float* b_ff2    = (const float*)d_in[16];
    const float* w_cls    = (const float*)d_in[17];
    const float* w_logits = (const float*)d_in[18];
    const float* b_logits = (const float*)d_in[19];
    float* out = (float*)d_out;

    float* p_qk    = sym(g_qk);
    float* p_qkp   = sym(g_qkp);
    float* p_vp    = sym(g_vp);
    float* p_ctx   = sym(g_ctx);
    float* p_tgt2  = sym(g_tgt2);
    float* p_pf1   = sym(g_pf1);
    float* p_params= sym(g_params);
    float* p_f2    = sym(g_f2);
    float* p_dynr  = sym(g_dynraw);
    float* p_pf2   = sym(g_pf2);
    float* p_pfB   = sym(g_pfB);
    float* p_ffh   = sym(g_ffh);
    float* p_t2    = sym(g_t2);
    float* p_fc    = sym(g_fc);
    float* p_g1    = sym(g_g1);
    float* p_clsf  = sym(g_clsf);

    // 1. IoU relation mask
    iou_mask_kernel<<<cdiv(NB * NRQ * NRQ, 256), 256>>>(bboxes, mask);
    // 2. qk = pro + query
    qkadd_kernel<<<cdiv(ROWS * DIM, 256), 256>>>(pro, query);
    // 3. q,k projection: [2400,512]
    {
        dim3 g(cdiv(512, 128), cdiv(ROWS, 128));
        sgemm_bias<<<g, 256>>>(p_qk, w_qkv, b_qkv, p_qkp, ROWS, 512, DIM, 0);
    }
    // 4. v projection from pro_features
    {
        dim3 g(cdiv(DIM, 128), cdiv(ROWS, 128));
        sgemm_bias<<<g, 256>>>(pro, w_qkv + 512 * DIM, b_qkv + 512, p_vp, ROWS, DIM, DIM, 0);
    }
    // 5-7. attention
    {
        dim3 g(cdiv(NRQ, 32), NHD, NB);
        scores_kernel<<<g, 256>>>();
    }
    softmax_kernel<<<cdiv(NB * NHD * NRQ, 8), 256>>>();
    ctx_kernel<<<cdiv(ROWS * DIM, 256), 256>>>();
    // 8. out proj
    {
        dim3 g(cdiv(DIM, 128), cdiv(ROWS, 128));
        sgemm_bias<<<g, 256>>>(p_ctx, w_attn, b_attn, p_tgt2, ROWS, DIM, DIM, 0);
    }
    // 9. norm1 + mask
    ln_kernel<<<ROWS, 256>>>(p_tgt2, pro, mask, p_pf1, 0);
    // 10. dyn params GEMM [2400, 32768]
    {
        dim3 g(cdiv(2 * DIM * DDI, 128), cdiv(ROWS, 128));
        sgemm_bias<<<g, 256>>>(p_pf1, w_dyn, b_dyn, p_params, ROWS, 2 * DIM * DDI, DIM, 0);
    }
    // 11. per-instance dynamic conv
    {
        int smem = (SS * DIM + DIM * DDI + SS * DDI) * 4;  // 128256 B
        cudaFuncSetAttribute(dynconv_kernel, cudaFuncAttributeMaxDynamicSharedMemorySize, smem);
        dynconv_kernel<<<ROWS, 256, smem>>>(roi);
    }
    // 12. out_layer GEMM: [2400,256], K=12544
    {
        dim3 g(cdiv(DIM, 128), cdiv(ROWS, 128));
        sgemm_bias<<<g, 256>>>(p_f2, w_dyno, b_dyno, p_dynr, ROWS, DIM, SS * DIM, 0);
    }
    // 13. pf2 = relu(ln(dynraw))
    ln_kernel<<<ROWS, 256>>>(p_dynr, nullptr, nullptr, p_pf2, 1);
    // 14. norm2: pfB = ln(pf1 + pf2)
    ln_kernel<<<ROWS, 256>>>(p_pf2, p_pf1, nullptr, p_pfB, 0);
    // 15. FFN 1 (relu)
    {
        dim3 g(cdiv(FFD, 128), cdiv(ROWS, 128));
        sgemm_bias<<<g, 256>>>(p_pfB, w_ff1, b_ff1, p_ffh, ROWS, FFD, DIM, 1);
    }
    // 16. FFN 2
    {
        dim3 g(cdiv(DIM, 128), cdiv(ROWS, 128));
        sgemm_bias<<<g, 256>>>(p_ffh, w_ff2, b_ff2, p_t2, ROWS, DIM, FFD, 0);
    }
    // 17. norm3 + mask -> fc
    ln_kernel<<<ROWS, 256>>>(p_t2, p_pfB, mask, p_fc, 0);
    // 18. cls tower linear (no bias)
    {
        dim3 g(cdiv(DIM, 128), cdiv(ROWS, 128));
        sgemm_bias<<<g, 256>>>(p_fc, w_cls, nullptr, p_g1, ROWS, DIM, DIM, 0);
    }
    // 19. cls_f = relu(ln(g1))
    ln_kernel<<<ROWS, 256>>>(p_g1, nullptr, nullptr, p_clsf, 1);
    // 20. logits -> d_out [2400, 80]
    {
        dim3 g(cdiv(NCLS, 128), cdiv(ROWS, 128));
        sgemm_bias<<<g, 256>>>(p_clsf, w_logits, b_logits, out, ROWS, NCLS, DIM, 0);
    }
}

// round 7
// speedup vs baseline: 1.9896x; 1.9896x over previous
#include <cuda_runtime.h>
#include <cstdint>
#include <cstddef>

#define NB   8
#define NRQ  300
#define DIM  256
#define NHD  8
#define HDM  32
#define SS   49
#define DDI  64
#define FFD  2048
#define NCLS 80
#define ROWS 2400   // NB*NRQ

// ------------------------- scratch (device globals) -------------------------
__device__ float g_qk   [ROWS * DIM];
__device__ float g_qkp  [ROWS * 512];                 // q proj | k proj
__device__ float g_vp   [ROWS * DIM];
__device__ float g_mflag[NB * NRQ * NRQ];             // 1 = masked
__device__ float g_scores[(size_t)NB * NHD * NRQ * NRQ];
__device__ float g_ctx  [ROWS * DIM];
__device__ float g_tgt2 [ROWS * DIM];
__device__ float g_pf1  [ROWS * DIM];
__device__ float g_params[(size_t)ROWS * 2 * DIM * DDI];   // 314 MB
__device__ float g_f2   [(size_t)ROWS * SS * DIM];         // 120 MB
__device__ float g_dynraw[ROWS * DIM];
__device__ float g_pf2  [ROWS * DIM];
__device__ float g_pfB  [ROWS * DIM];
__device__ float g_ffh  [(size_t)ROWS * FFD];
__device__ float g_t2   [ROWS * DIM];
__device__ float g_fc   [ROWS * DIM];
__device__ float g_g1   [ROWS * DIM];
__device__ float g_clsf [ROWS * DIM];

static inline int cdiv(int a, int b) { return (a + b - 1) / b; }

// ------------------------- TF32 tensor-core GEMM ----------------------------
// C = A * B^T + bias, optional relu.
// A [M,K] row-major, B [N,K] row-major (torch Linear weight). K % 32 == 0.
// CTA tile 128x128x32, 8 warps, warp tile 64x32 via m16n8k8 tf32 HMMA.
#define BM 128
#define BN 128
#define BK 32
#define SMS 136   // smem row stride (floats): bank = 8*(lane%4)+lane/4, conflict-free

__device__ __forceinline__ uint32_t f2tf32(float f) {
    uint32_t u;
    asm("cvt.rna.tf32.f32 %0, %1;" : "=r"(u) : "f"(f));
    return u;
}

__global__ __launch_bounds__(256) void gemm_tf32(
    const float* __restrict__ A, const float* __restrict__ B,
    const float* __restrict__ bias, float* __restrict__ C,
    int M, int N, int K, int relu)
{
    __shared__ float As[BK * SMS];   // [k][m]
    __shared__ float Bs[BK * SMS];   // [k][n]

    int tid = threadIdx.x;
    int lane = tid & 31;
    int wid = tid >> 5;
    int wm = wid & 1;        // 2 warps along M, 64 rows each
    int wn = wid >> 1;       // 4 warps along N, 32 cols each
    int bm = blockIdx.y * BM;
    int bn = blockIdx.x * BN;

    int tg = lane & 3;       // thread-in-group (k offset)
    int gp = lane >> 2;      // group id (row/col offset)

    float c[4][4][4];
#pragma unroll
    for (int mi = 0; mi < 4; mi++)
#pragma unroll
        for (int ni = 0; ni < 4; ni++)
#pragma unroll
            for (int r = 0; r < 4; r++) c[mi][ni][r] = 0.f;

    for (int k0 = 0; k0 < K; k0 += BK) {
        // --- load A tile [BM][BK] -> As[k][m], float4 per thread x4 ---
#pragma unroll
        for (int i = 0; i < 4; i++) {
            int g = tid + i * 256;          // 0..1023 float4 groups
            int row = g >> 3;               // 0..127
            int kc = (g & 7) << 2;          // 0,4,...,28
            float4 v = make_float4(0.f, 0.f, 0.f, 0.f);
            int gr = bm + row;
            if (gr < M) v = *(const float4*)(A + (size_t)gr * K + k0 + kc);
            As[(kc + 0) * SMS + row] = v.x;
            As[(kc + 1) * SMS + row] = v.y;
            As[(kc + 2) * SMS + row] = v.z;
            As[(kc + 3) * SMS + row] = v.w;
        }
        // --- load B tile [BN][BK] -> Bs[k][n] ---
#pragma unroll
        for (int i = 0; i < 4; i++) {
            int g = tid + i * 256;
            int row = g >> 3;
            int kc = (g & 7) << 2;
            float4 v = make_float4(0.f, 0.f, 0.f, 0.f);
            int gn = bn + row;
            if (gn < N) v = *(const float4*)(B + (size_t)gn * K + k0 + kc);
            Bs[(kc + 0) * SMS + row] = v.x;
            Bs[(kc + 1) * SMS + row] = v.y;
            Bs[(kc + 2) * SMS + row] = v.z;
            Bs[(kc + 3) * SMS + row] = v.w;
        }
        __syncthreads();

#pragma unroll
        for (int ks = 0; ks < 4; ks++) {
            int k8 = ks * 8;
            uint32_t af[4][4], bf[4][2];
#pragma unroll
            for (int mi = 0; mi < 4; mi++) {
                int m = wm * 64 + mi * 16 + gp;
                af[mi][0] = f2tf32(As[(k8 + tg) * SMS + m]);
                af[mi][1] = f2tf32(As[(k8 + tg) * SMS + m + 8]);
                af[mi][2] = f2tf32(As[(k8 + tg + 4) * SMS + m]);
                af[mi][3] = f2tf32(As[(k8 + tg + 4) * SMS + m + 8]);
            }
#pragma unroll
            for (int ni = 0; ni < 4; ni++) {
                int n = wn * 32 + ni * 8 + gp;
                bf[ni][0] = f2tf32(Bs[(k8 + tg) * SMS + n]);
                bf[ni][1] = f2tf32(Bs[(k8 + tg + 4) * SMS + n]);
            }
#pragma unroll
            for (int mi = 0; mi < 4; mi++)
#pragma unroll
                for (int ni = 0; ni < 4; ni++) {
                    asm volatile(
                        "mma.sync.aligned.m16n8k8.row.col.f32.tf32.tf32.f32 "
                        "{%0,%1,%2,%3}, {%4,%5,%6,%7}, {%8,%9}, {%0,%1,%2,%3};"
                        : "+f"(c[mi][ni][0]), "+f"(c[mi][ni][1]),
                          "+f"(c[mi][ni][2]), "+f"(c[mi][ni][3])
                        : "r"(af[mi][0]), "r"(af[mi][1]), "r"(af[mi][2]), "r"(af[mi][3]),
                          "r"(bf[ni][0]), "r"(bf[ni][1]));
                }
        }
        __syncthreads();
    }

    // --- epilogue ---
#pragma unroll
    for (int mi = 0; mi < 4; mi++) {
        int r0 = bm + wm * 64 + mi * 16 + gp;
#pragma unroll
        for (int ni = 0; ni < 4; ni++) {
            int col = bn + wn * 32 + ni * 8 + 2 * tg;
            if (col >= N) continue;
            float b0 = bias ? bias[col] : 0.f;
            float b1 = bias ? bias[col + 1] : 0.f;
            if (r0 < M) {
                float v0 = c[mi][ni][0] + b0;
                float v1 = c[mi][ni][1] + b1;
                if (relu) { v0 = fmaxf(v0, 0.f); v1 = fmaxf(v1, 0.f); }
                *(float2*)(C + (size_t)r0 * N + col) = make_float2(v0, v1);
            }
            if (r0 + 8 < M) {
                float v2 = c[mi][ni][2] + b0;
                float v3 = c[mi][ni][3] + b1;
                if (relu) { v2 = fmaxf(v2, 0.f); v3 = fmaxf(v3, 0.f); }
                *(float2*)(C + (size_t)(r0 + 8) * N + col) = make_float2(v2, v3);
            }
        }
    }
}

// ------------------------- IoU relation mask --------------------------------
__global__ void iou_mask_kernel(const float* __restrict__ bboxes,
                                const float* __restrict__ mask)
{
    int idx = blockIdx.x * blockDim.x + threadIdx.x;
    if (idx >= NB * NRQ * NRQ) return;
    int j = idx % NRQ;
    int i = (idx / NRQ) % NRQ;
    int n = idx / (NRQ * NRQ);
    const float* bi = bboxes + (size_t)(n * NRQ + i) * 4;
    const float* bj = bboxes + (size_t)(n * NRQ + j) * 4;
    float ax0 = bi[0], ay0 = bi[1], ax1 = bi[2], ay1 = bi[3];
    float bx0 = bj[0], by0 = bj[1], bx1 = bj[2], by1 = bj[3];
    float areaA = (ax1 - ax0) * (ay1 - ay0);
    float areaB = (bx1 - bx0) * (by1 - by0);
    float lx = fmaxf(ax0, bx0), ly = fmaxf(ay0, by0);
    float rx = fminf(ax1, bx1), ry = fminf(ay1, by1);
    float w = fmaxf(rx - lx, 0.f), h = fmaxf(ry - ly, 0.f);
    float inter = w * h;
    float uni = areaA + areaB - inter;
    float iou = inter / fmaxf(uni, 1e-9f);
    float mi = mask[n * NRQ + i], mj = mask[n * NRQ + j];
    bool masked = ((iou < 0.5f) && mi > 0.f && mj > 0.f) || (i == j && mi == 0.f);
    g_mflag[idx] = masked ? 1.f : 0.f;
}

// ------------------------- qk = pro + query ---------------------------------
__global__ void qkadd_kernel(const float* __restrict__ pro, const float* __restrict__ query)
{
    int idx = blockIdx.x * blockDim.x + threadIdx.x;
    if (idx >= ROWS * DIM) return;
    g_qk[idx] = pro[idx] + query[idx];
}

// ------------------------- attention scores ---------------------------------
__global__ void scores_kernel()
{
    int n = blockIdx.z, h = blockIdx.y, qt = blockIdx.x * 32;
    __shared__ float Qs[32][32];
    __shared__ float Ks[32][33];
    int tid = threadIdx.x;
    int r = tid / 32, c = tid % 32;
    for (int rr = r; rr < 32; rr += 8) {
        int q = qt + rr;
        Qs[rr][c] = (q < NRQ) ? g_qkp[(size_t)(n * NRQ + q) * 512 + h * 32 + c] : 0.f;
    }
    const float scale = 0.17677669529663687f;  // 1/sqrt(32)
    for (int kt = 0; kt < NRQ; kt += 32) {
        __syncthreads();
        for (int rr = r; rr < 32; rr += 8) {
            int k = kt + rr;
            Ks[rr][c] = (k < NRQ) ? g_qkp[(size_t)(n * NRQ + k) * 512 + 256 + h * 32 + c] : 0.f;
        }
        __syncthreads();
        int kk = tid % 32, qr0 = tid / 32;
        float acc[4] = {0.f, 0.f, 0.f, 0.f};
#pragma unroll
        for (int d = 0; d < 32; d++) {
            float kv = Ks[kk][d];
#pragma unroll
            for (int u = 0; u < 4; u++) acc[u] += Qs[qr0 + u * 8][d] * kv;
        }
#pragma unroll
        for (int u = 0; u < 4; u++) {
            int q = qt + qr0 + u * 8;
            int k = kt + kk;
            if (q < NRQ && k < NRQ) {
                float flag = g_mflag[(size_t)(n * NRQ + q) * NRQ + k];
                size_t off = ((size_t)(n * NHD + h) * NRQ + q) * NRQ + k;
                g_scores[off] = (flag > 0.f) ? -1e9f : acc[u] * scale;
            }
        }
    }
}

// ------------------------- row softmax (one warp per row) -------------------
__global__ void softmax_kernel()
{
    int row = blockIdx.x * 8 + threadIdx.x / 32;
    int lane = threadIdx.x % 32;
    if (row >= NB * NHD * NRQ) return;
    float* p = g_scores + (size_t)row * NRQ;
    float mx = -1e30f;
    for (int k = lane; k < NRQ; k += 32) mx = fmaxf(mx, p[k]);
    for (int o = 16; o; o >>= 1) mx = fmaxf(mx, __shfl_xor_sync(0xffffffffu, mx, o));
    float sum = 0.f;
    for (int k = lane; k < NRQ; k += 32) { float e = __expf(p[k] - mx); p[k] = e; sum += e; }
    for (int o = 16; o; o >>= 1) sum += __shfl_xor_sync(0xffffffffu, sum, o);
    float inv = 1.f / sum;
    for (int k = lane; k < NRQ; k += 32) p[k] *= inv;
}

// ------------------------- ctx = attn @ V -----------------------------------
__global__ void ctx_kernel()
{
    int idx = blockIdx.x * blockDim.x + threadIdx.x;
    if (idx >= ROWS * DIM) return;
    int col = idx & 255;
    int row = idx >> 8;             // n*NRQ + q
    int n = row / NRQ, q = row % NRQ;
    int h = col >> 5;
    const float* ap = g_scores + ((size_t)(n * NHD + h) * NRQ + q) * NRQ;
    float acc = 0.f;
    for (int k = 0; k < NRQ; k++)
        acc += ap[k] * g_vp[(size_t)(n * NRQ + k) * DIM + col];
    g_ctx[idx] = acc;
}

// ------------------------- LayerNorm rows of 256 ----------------------------
__global__ void ln_kernel(const float* __restrict__ x, const float* __restrict__ res,
                          const float* __restrict__ mask, float* __restrict__ out, int relu)
{
    int row = blockIdx.x;
    int c = threadIdx.x;
    size_t base = (size_t)row * DIM;
    float v = x[base + c];
    if (res) v += res[base + c];
    float s = v, q = v * v;
    for (int o = 16; o; o >>= 1) {
        s += __shfl_xor_sync(0xffffffffu, s, o);
        q += __shfl_xor_sync(0xffffffffu, q, o);
    }
    __shared__ float ss[8], sq[8];
    int w = c >> 5, lane = c & 31;
    if (lane == 0) { ss[w] = s; sq[w] = q; }
    __syncthreads();
    float tot = 0.f, totq = 0.f;
#pragma unroll
    for (int i = 0; i < 8; i++) { tot += ss[i]; totq += sq[i]; }
    float mean = tot * (1.f / DIM);
    float var = totq * (1.f / DIM) - mean * mean;
    float y = (v - mean) * rsqrtf(var + 1e-5f);
    if (relu) y = fmaxf(y, 0.f);
    if (mask) y *= mask[row];
    out[base + c] = y;
}

// ------------------------- DynamicConv per instance -------------------------
__global__ __launch_bounds__(256) void dynconv_kernel(const float* __restrict__ roi)
{
    extern __shared__ float sm[];
    float* fsm  = sm;                 // 12544
    float* psm  = sm + 12544;         // 16384
    float* f1sm = psm + 16384;        // 3136
    int n = blockIdx.x, tid = threadIdx.x;

    for (int i = tid; i < SS * DIM; i += 256) {
        int s = i >> 8, d = i & 255;
        fsm[i] = roi[((size_t)s * ROWS + n) * DIM + d];
    }
    const float* pr = g_params + (size_t)n * (2 * DIM * DDI);
    for (int i = tid; i < DIM * DDI; i += 256) psm[i] = pr[i];
    __syncthreads();

    int e = tid & 63, sb = tid >> 6;
    for (int s = sb; s < SS; s += 4) {
        float acc = 0.f;
        const float* fr = fsm + s * DIM;
#pragma unroll 8
        for (int d = 0; d < DIM; d++) acc += fr[d] * psm[d * DDI + e];
        f1sm[s * DDI + e] = acc;
    }
    __syncthreads();

    int wid = tid >> 5, lane = tid & 31;
    for (int s = wid; s < SS; s += 8) {
        float a = f1sm[s * DDI + lane], b = f1sm[s * DDI + 32 + lane];
        float sum = a + b, ssq = a * a + b * b;
        for (int o = 16; o; o >>= 1) {
            sum += __shfl_xor_sync(0xffffffffu, sum, o);
            ssq += __shfl_xor_sync(0xffffffffu, ssq, o);
        }
        float mean = sum * (1.f / 64.f);
        float var = ssq * (1.f / 64.f) - mean * mean;
        float inv = rsqrtf(var + 1e-5f);
        f1sm[s * DDI + lane]      = fmaxf((a - mean) * inv, 0.f);
        f1sm[s * DDI + 32 + lane] = fmaxf((b - mean) * inv, 0.f);
    }
    for (int i = tid; i < DIM * DDI; i += 256) psm[i] = pr[DIM * DDI + i];
    __syncthreads();

    for (int s = 0; s < SS; s++) {
        float acc = 0.f;
#pragma unroll 8
        for (int ee = 0; ee < DDI; ee++) acc += f1sm[s * DDI + ee] * psm[ee * DIM + tid];
        fsm[s * DIM + tid] = acc;
    }
    __syncthreads();

    for (int s = wid; s < SS; s += 8) {
        float vals[8];
        float sum = 0.f, ssq = 0.f;
#pragma unroll
        for (int u = 0; u < 8; u++) {
            float v = fsm[s * DIM + lane + u * 32];
            vals[u] = v; sum += v; ssq += v * v;
        }
        for (int o = 16; o; o >>= 1) {
            sum += __shfl_xor_sync(0xffffffffu, sum, o);
            ssq += __shfl_xor_sync(0xffffffffu, ssq, o);
        }
        float mean = sum * (1.f / DIM);
        float var = ssq * (1.f / DIM) - mean * mean;
        float inv = rsqrtf(var + 1e-5f);
#pragma unroll
        for (int u = 0; u < 8; u++) {
            float y = fmaxf((vals[u] - mean) * inv, 0.f);
            g_f2[(size_t)n * (SS * DIM) + s * DIM + lane + u * 32] = y;
        }
    }
}

// ------------------------- host launch --------------------------------------
template <typename T>
static float* sym(T& s) { void* p = nullptr; cudaGetSymbolAddress(&p, s); return (float*)p; }

extern "C" void kernel_launch(void* const* d_in, const int* in_sizes, int n_in,
                              void* d_out, int out_size)
{
    const float* bboxes   = (const float*)d_in[0];
    const float* pro      = (const float*)d_in[1];
    const float* roi      = (const float*)d_in[2];
    const float* query    = (const float*)d_in[3];
    const float* mask     = (const float*)d_in[4];
    const float* w_qkv    = (const float*)d_in[5];
    const float* b_qkv    = (const float*)d_in[6];
    const float* w_attn   = (const float*)d_in[7];
    const float* b_attn   = (const float*)d_in[8];
    const float* w_dyn    = (const float*)d_in[9];
    const float* b_dyn    = (const float*)d_in[10];
    const float* w_dyno   = (const float*)d_in[11];
    const float* b_dyno   = (const float*)d_in[12];
    const float* w_ff1    = (const float*)d_in[13];
    const float* b_ff1    = (const float*)d_in[14];
    const float* w_ff2    = (const float*)d_in[15];
    const float* b_ff2    = (const float*)d_in[16];
    const float* w_cls    = (const float*)d_in[17];
    const float* w_logits = (const float*)d_in[18];
    const float* b_logits = (const float*)d_in[19];
    float* out = (float*)d_out;

    float* p_qk    = sym(g_qk);
    float* p_qkp   = sym(g_qkp);
    float* p_vp    = sym(g_vp);
    float* p_ctx   = sym(g_ctx);
    float* p_tgt2  = sym(g_tgt2);
    float* p_pf1   = sym(g_pf1);
    float* p_params= sym(g_params);
    float* p_f2    = sym(g_f2);
    float* p_dynr  = sym(g_dynraw);
    float* p_pf2   = sym(g_pf2);
    float* p_pfB   = sym(g_pfB);
    float* p_ffh   = sym(g_ffh);
    float* p_t2    = sym(g_t2);
    float* p_fc    = sym(g_fc);
    float* p_g1    = sym(g_g1);
    float* p_clsf  = sym(g_clsf);

    // 1. IoU relation mask
    iou_mask_kernel<<<cdiv(NB * NRQ * NRQ, 256), 256>>>(bboxes, mask);
    // 2. qk = pro + query
    qkadd_kernel<<<cdiv(ROWS * DIM, 256), 256>>>(pro, query);
    // 3. q,k projection: [2400,512]
    {
        dim3 g(cdiv(512, BN), cdiv(ROWS, BM));
        gemm_tf32<<<g, 256>>>(p_qk, w_qkv, b_qkv, p_qkp, ROWS, 512, DIM, 0);
    }
    // 4. v projection from pro_features
    {
        dim3 g(cdiv(DIM, BN), cdiv(ROWS, BM));
        gemm_tf32<<<g, 256>>>(pro, w_qkv + 512 * DIM, b_qkv + 512, p_vp, ROWS, DIM, DIM, 0);
    }
    // 5-7. attention
    {
        dim3 g(cdiv(NRQ, 32), NHD, NB);
        scores_kernel<<<g, 256>>>();
    }
    softmax_kernel<<<cdiv(NB * NHD * NRQ, 8), 256>>>();
    ctx_kernel<<<cdiv(ROWS * DIM, 256), 256>>>();
    // 8. out proj
    {
        dim3 g(cdiv(DIM, BN), cdiv(ROWS, BM));
        gemm_tf32<<<g, 256>>>(p_ctx, w_attn, b_attn, p_tgt2, ROWS, DIM, DIM, 0);
    }
    // 9. norm1 + mask
    ln_kernel<<<ROWS, 256>>>(p_tgt2, pro, mask, p_pf1, 0);
    // 10. dyn params GEMM [2400, 32768]
    {
        dim3 g(cdiv(2 * DIM * DDI, BN), cdiv(ROWS, BM));
        gemm_tf32<<<g, 256>>>(p_pf1, w_dyn, b_dyn, p_params, ROWS, 2 * DIM * DDI, DIM, 0);
    }
    // 11. per-instance dynamic conv
    {
        int smem = (SS * DIM + DIM * DDI + SS * DDI) * 4;  // 128256 B
        cudaFuncSetAttribute(dynconv_kernel, cudaFuncAttributeMaxDynamicSharedMemorySize, smem);
        dynconv_kernel<<<ROWS, 256, smem>>>(roi);
    }
    // 12. out_layer GEMM: [2400,256], K=12544
    {
        dim3 g(cdiv(DIM, BN), cdiv(ROWS, BM));
        gemm_tf32<<<g, 256>>>(p_f2, w_dyno, b_dyno, p_dynr, ROWS, DIM, SS * DIM, 0);
    }
    // 13. pf2 = relu(ln(dynraw))
    ln_kernel<<<ROWS, 256>>>(p_dynr, nullptr, nullptr, p_pf2, 1);
    // 14. norm2: pfB = ln(pf1 + pf2)
    ln_kernel<<<ROWS, 256>>>(p_pf2, p_pf1, nullptr, p_pfB, 0);
    // 15. FFN 1 (relu)
    {
        dim3 g(cdiv(FFD, BN), cdiv(ROWS, BM));
        gemm_tf32<<<g, 256>>>(p_pfB, w_ff1, b_ff1, p_ffh, ROWS, FFD, DIM, 1);
    }
    // 16. FFN 2
    {
        dim3 g(cdiv(DIM, BN), cdiv(ROWS, BM));
        gemm_tf32<<<g, 256>>>(p_ffh, w_ff2, b_ff2, p_t2, ROWS, DIM, FFD, 0);
    }
    // 17. norm3 + mask -> fc
    ln_kernel<<<ROWS, 256>>>(p_t2, p_pfB, mask, p_fc, 0);
    // 18. cls tower linear (no bias)
    {
        dim3 g(cdiv(DIM, BN), cdiv(ROWS, BM));
        gemm_tf32<<<g, 256>>>(p_fc, w_cls, nullptr, p_g1, ROWS, DIM, DIM, 0);
    }
    // 19. cls_f = relu(ln(g1))
    ln_kernel<<<ROWS, 256>>>(p_g1, nullptr, nullptr, p_clsf, 1);
    // 20. logits -> d_out [2400, 80]
    {
        dim3 g(cdiv(NCLS, BN), cdiv(ROWS, BM));
        gemm_tf32<<<g, 256>>>(p_clsf, w_logits, b_logits, out, ROWS, NCLS, DIM, 0);
    }
}

// round 8
// speedup vs baseline: 2.6994x; 1.3567x over previous
#include <cuda_runtime.h>
#include <cstdint>
#include <cstddef>

#define NB   8
#define NRQ  300
#define DIM  256
#define NHD  8
#define HDM  32
#define SS   49
#define DDI  64
#define FFD  2048
#define NCLS 80
#define ROWS 2400   // NB*NRQ

// ------------------------- scratch (device globals) -------------------------
__device__ float g_qk   [ROWS * DIM];
__device__ float g_qkp  [ROWS * 512];                 // q proj | k proj
__device__ float g_vp   [ROWS * DIM];
__device__ float g_mflag[NB * NRQ * NRQ];             // 1 = masked
__device__ float g_scores[(size_t)NB * NHD * NRQ * NRQ];
__device__ float g_ctx  [ROWS * DIM];
__device__ float g_tgt2 [ROWS * DIM];
__device__ float g_pf1  [ROWS * DIM];
__device__ float g_params[(size_t)ROWS * 2 * DIM * DDI];   // 314 MB (also split-K scratch)
__device__ float g_f2   [(size_t)ROWS * SS * DIM];         // 120 MB
__device__ float g_dynraw[ROWS * DIM];
__device__ float g_pf2  [ROWS * DIM];
__device__ float g_pfB  [ROWS * DIM];
__device__ float g_ffh  [(size_t)ROWS * FFD];
__device__ float g_t2   [ROWS * DIM];
__device__ float g_fc   [ROWS * DIM];
__device__ float g_g1   [ROWS * DIM];
__device__ float g_clsf [ROWS * DIM];

static inline int cdiv(int a, int b) { return (a + b - 1) / b; }

// ------------------------- TF32 tensor-core GEMM v2 -------------------------
// C = A * B^T (+bias) (optional relu). A[M,K] rm (row stride lda),
// B[N,K] rm (row stride ldb). kChunk % 32 == 0. blockIdx.z = split-K slice:
// A,B advance by z*kChunk along k; C advances by z*M*N.
//
// CTA tile 128x128x32, 8 warps (2m x 4n), warp tile 64x32, m16n8k8 tf32.
// Smem holds tiles in FRAGMENT ORDER (tf32-converted):
//   A chunk c = ks*8 + wm*4 + mi   (32 chunks of 128 words)
//   B chunk c = ks*8 + wn*2 + h    (32 chunks of 128 words)
//   word addr = c*128 + lane*4 + r  -> LDS.128 / STS.128 conflict-free.
#define BM 128
#define BN 128
#define BK 32

__device__ __forceinline__ uint32_t f2tf32(float f) {
    uint32_t u;
    asm("cvt.rna.tf32.f32 %0, %1;" : "=r"(u) : "f"(f));
    return u;
}

__global__ __launch_bounds__(256) void gemm_tf32(
    const float* __restrict__ A, const float* __restrict__ B,
    const float* __restrict__ bias, float* __restrict__ C,
    int M, int N, int kChunk, int lda, int ldb, int relu)
{
    extern __shared__ uint32_t dynsm[];           // [2][8192]: A at +0, B at +4096
    int tid = threadIdx.x;
    int lane = tid & 31;
    int wrp = tid >> 5;
    int gp = lane >> 2, tg = lane & 3;
    int bm = blockIdx.y * BM, bn = blockIdx.x * BN;

    // split-K slice offsets
    A += (size_t)blockIdx.z * kChunk;
    B += (size_t)blockIdx.z * kChunk;
    C += (size_t)blockIdx.z * M * N;

    int wm = wrp & 1, wn = wrp >> 1;

    float c[4][4][4];
#pragma unroll
    for (int mi = 0; mi < 4; mi++)
#pragma unroll
        for (int ni = 0; ni < 4; ni++)
#pragma unroll
            for (int r = 0; r < 4; r++) c[mi][ni][r] = 0.f;

    // ---- loader precompute: each warp owns chunks {wrp, wrp+8, wrp+16, wrp+24}
    const float* aptr[4]; bool aok0[4], aok1[4]; int stsoff[4];
    const float* bptr[4]; bool bok0[4], bok1[4];
#pragma unroll
    for (int i = 0; i < 4; i++) {
        int cc = wrp + 8 * i;
        stsoff[i] = (cc << 7) + (lane << 2);
        // A: ks=cc>>3, wm_c=(cc>>2)&1, mi=cc&3
        {
            int ks = cc >> 3, wmc = (cc >> 2) & 1, mi = cc & 3;
            int row = wmc * 64 + mi * 16 + gp;
            int kk = ks * 8 + tg;
            aptr[i] = A + (size_t)(bm + row) * lda + kk;
            aok0[i] = (bm + row) < M;
            aok1[i] = (bm + row + 8) < M;
        }
        // B: ks=cc>>3, wn_c=(cc&7)>>1, h=cc&1
        {
            int ks = cc >> 3, wnc = (cc & 7) >> 1, h = cc & 1;
            int col = wnc * 32 + h * 16 + gp;     // ni base = 2h -> +16 cols
            int kk = ks * 8 + tg;
            bptr[i] = B + (size_t)(bn + col) * ldb + kk;
            bok0[i] = (bn + col) < N;
            bok1[i] = (bn + col + 8) < N;
        }
    }

    int nk = kChunk / BK;
    float4 ra[4], rb[4];

    // regs->smem store lambdas
    auto stsA = [&](int s) {
#pragma unroll
        for (int i = 0; i < 4; i++) {
            uint4 u;
            u.x = f2tf32(ra[i].x); u.y = f2tf32(ra[i].y);
            u.z = f2tf32(ra[i].z); u.w = f2tf32(ra[i].w);
            *(uint4*)&dynsm[s * 8192 + stsoff[i]] = u;
        }
    };
    auto stsB = [&](int s) {
#pragma unroll
        for (int i = 0; i < 4; i++) {
            uint4 u;
            u.x = f2tf32(rb[i].x); u.y = f2tf32(rb[i].y);
            u.z = f2tf32(rb[i].z); u.w = f2tf32(rb[i].w);
            *(uint4*)&dynsm[s * 8192 + 4096 + stsoff[i]] = u;
        }
    };
    auto ldgA = [&]() {
#pragma unroll
        for (int i = 0; i < 4; i++) {
            const float* p = aptr[i];
            ra[i].x = aok0[i] ? p[0] : 0.f;                  // (row,   k  ) -> a0
            ra[i].y = aok1[i] ? p[(size_t)8 * lda] : 0.f;    // (row+8, k  ) -> a1
            ra[i].z = aok0[i] ? p[4] : 0.f;                  // (row,   k+4) -> a2
            ra[i].w = aok1[i] ? p[(size_t)8 * lda + 4] : 0.f;// (row+8, k+4) -> a3
            aptr[i] += BK;
        }
    };
    auto ldgB = [&]() {
#pragma unroll
        for (int i = 0; i < 4; i++) {
            const float* p = bptr[i];
            rb[i].x = bok0[i] ? p[0] : 0.f;                  // (col,   k  )
            rb[i].y = bok0[i] ? p[4] : 0.f;                  // (col,   k+4)
            rb[i].z = bok1[i] ? p[(size_t)8 * ldb] : 0.f;    // (col+8, k  )
            rb[i].w = bok1[i] ? p[(size_t)8 * ldb + 4] : 0.f;// (col+8, k+4)
            bptr[i] += BK;
        }
    };
    auto compute = [&](int s, int ks) {
        const uint32_t* smA = dynsm + s * 8192;
        const uint32_t* smB = smA + 4096;
        uint4 av[4];
#pragma unroll
        for (int mi = 0; mi < 4; mi++)
            av[mi] = *(const uint4*)&smA[((ks * 8 + wm * 4 + mi) << 7) + (lane << 2)];
        uint4 bv0 = *(const uint4*)&smB[((ks * 8 + wn * 2 + 0) << 7) + (lane << 2)];
        uint4 bv1 = *(const uint4*)&smB[((ks * 8 + wn * 2 + 1) << 7) + (lane << 2)];
        uint32_t bf[4][2] = {{bv0.x, bv0.y}, {bv0.z, bv0.w}, {bv1.x, bv1.y}, {bv1.z, bv1.w}};
#pragma unroll
        for (int mi = 0; mi < 4; mi++)
#pragma unroll
            for (int ni = 0; ni < 4; ni++) {
                asm volatile(
                    "mma.sync.aligned.m16n8k8.row.col.f32.tf32.tf32.f32 "
                    "{%0,%1,%2,%3}, {%4,%5,%6,%7}, {%8,%9}, {%0,%1,%2,%3};"
                    : "+f"(c[mi][ni][0]), "+f"(c[mi][ni][1]),
                      "+f"(c[mi][ni][2]), "+f"(c[mi][ni][3])
                    : "r"(av[mi].x), "r"(av[mi].y), "r"(av[mi].z), "r"(av[mi].w),
                      "r"(bf[ni][0]), "r"(bf[ni][1]));
            }
    };

    // prologue: tile 0 -> stage 0
    ldgA(); ldgB();
    stsA(0); stsB(0);
    __syncthreads();

    int s = 0;
    for (int kt = 0; kt < nk; kt++) {
        bool nxt = (kt + 1) < nk;
        if (nxt) ldgA();
        compute(s, 0);
        compute(s, 1);
        if (nxt) { stsA(s ^ 1); ldgB(); }
        compute(s, 2);
        compute(s, 3);
        if (nxt) stsB(s ^ 1);
        __syncthreads();
        s ^= 1;
    }

    // --- epilogue ---
#pragma unroll
    for (int mi = 0; mi < 4; mi++) {
        int r0 = bm + wm * 64 + mi * 16 + gp;
#pragma unroll
        for (int ni = 0; ni < 4; ni++) {
            int col = bn + wn * 32 + ni * 8 + 2 * tg;
            if (col >= N) continue;
            float b0 = bias ? bias[col] : 0.f;
            float b1 = bias ? bias[col + 1] : 0.f;
            if (r0 < M) {
                float v0 = c[mi][ni][0] + b0;
                float v1 = c[mi][ni][1] + b1;
                if (relu) { v0 = fmaxf(v0, 0.f); v1 = fmaxf(v1, 0.f); }
                *(float2*)(C + (size_t)r0 * N + col) = make_float2(v0, v1);
            }
            if (r0 + 8 < M) {
                float v2 = c[mi][ni][2] + b0;
                float v3 = c[mi][ni][3] + b1;
                if (relu) { v2 = fmaxf(v2, 0.f); v3 = fmaxf(v3, 0.f); }
                *(float2*)(C + (size_t)(r0 + 8) * N + col) = make_float2(v2, v3);
            }
        }
    }
}

// split-K reduce: out[i] = sum_s part[s*MN+i] (+ bias[i%N]); fixed order => deterministic
__global__ void splitk_reduce(const float* __restrict__ part, const float* __restrict__ bias,
                              float* __restrict__ out, int MN, int N, int S)
{
    int i = blockIdx.x * 256 + threadIdx.x;
    if (i >= MN) return;
    float acc = bias ? bias[i & (N - 1)] : 0.f;   // N power of 2 here
    for (int si = 0; si < S; si++) acc += part[(size_t)si * MN + i];
    out[i] = acc;
}

// ------------------------- IoU relation mask --------------------------------
__global__ void iou_mask_kernel(const float* __restrict__ bboxes,
                                const float* __restrict__ mask)
{
    int idx = blockIdx.x * blockDim.x + threadIdx.x;
    if (idx >= NB * NRQ * NRQ) return;
    int j = idx % NRQ;
    int i = (idx / NRQ) % NRQ;
    int n = idx / (NRQ * NRQ);
    const float* bi = bboxes + (size_t)(n * NRQ + i) * 4;
    const float* bj = bboxes + (size_t)(n * NRQ + j) * 4;
    float ax0 = bi[0], ay0 = bi[1], ax1 = bi[2], ay1 = bi[3];
    float bx0 = bj[0], by0 = bj[1], bx1 = bj[2], by1 = bj[3];
    float areaA = (ax1 - ax0) * (ay1 - ay0);
    float areaB = (bx1 - bx0) * (by1 - by0);
    float lx = fmaxf(ax0, bx0), ly = fmaxf(ay0, by0);
    float rx = fminf(ax1, bx1), ry = fminf(ay1, by1);
    float w = fmaxf(rx - lx, 0.f), h = fmaxf(ry - ly, 0.f);
    float inter = w * h;
    float uni = areaA + areaB - inter;
    float iou = inter / fmaxf(uni, 1e-9f);
    float mi = mask[n * NRQ + i], mj = mask[n * NRQ + j];
    bool masked = ((iou < 0.5f) && mi > 0.f && mj > 0.f) || (i == j && mi == 0.f);
    g_mflag[idx] = masked ? 1.f : 0.f;
}

// ------------------------- qk = pro + query ---------------------------------
__global__ void qkadd_kernel(const float* __restrict__ pro, const float* __restrict__ query)
{
    int idx = blockIdx.x * blockDim.x + threadIdx.x;
    if (idx >= ROWS * DIM) return;
    g_qk[idx] = pro[idx] + query[idx];
}

// ------------------------- attention scores ---------------------------------
__global__ void scores_kernel()
{
    int n = blockIdx.z, h = blockIdx.y, qt = blockIdx.x * 32;
    __shared__ float Qs[32][32];
    __shared__ float Ks[32][33];
    int tid = threadIdx.x;
    int r = tid / 32, c = tid % 32;
    for (int rr = r; rr < 32; rr += 8) {
        int q = qt + rr;
        Qs[rr][c] = (q < NRQ) ? g_qkp[(size_t)(n * NRQ + q) * 512 + h * 32 + c] : 0.f;
    }
    const float scale = 0.17677669529663687f;  // 1/sqrt(32)
    for (int kt = 0; kt < NRQ; kt += 32) {
        __syncthreads();
        for (int rr = r; rr < 32; rr += 8) {
            int k = kt + rr;
            Ks[rr][c] = (k < NRQ) ? g_qkp[(size_t)(n * NRQ + k) * 512 + 256 + h * 32 + c] : 0.f;
        }
        __syncthreads();
        int kk = tid % 32, qr0 = tid / 32;
        float acc[4] = {0.f, 0.f, 0.f, 0.f};
#pragma unroll
        for (int d = 0; d < 32; d++) {
            float kv = Ks[kk][d];
#pragma unroll
            for (int u = 0; u < 4; u++) acc[u] += Qs[qr0 + u * 8][d] * kv;
        }
#pragma unroll
        for (int u = 0; u < 4; u++) {
            int q = qt + qr0 + u * 8;
            int k = kt + kk;
            if (q < NRQ && k < NRQ) {
                float flag = g_mflag[(size_t)(n * NRQ + q) * NRQ + k];
                size_t off = ((size_t)(n * NHD + h) * NRQ + q) * NRQ + k;
                g_scores[off] = (flag > 0.f) ? -1e9f : acc[u] * scale;
            }
        }
    }
}

// ------------------------- row softmax (one warp per row) -------------------
__global__ void softmax_kernel()
{
    int row = blockIdx.x * 8 + threadIdx.x / 32;
    int lane = threadIdx.x % 32;
    if (row >= NB * NHD * NRQ) return;
    float* p = g_scores + (size_t)row * NRQ;
    float mx = -1e30f;
    for (int k = lane; k < NRQ; k += 32) mx = fmaxf(mx, p[k]);
    for (int o = 16; o; o >>= 1) mx = fmaxf(mx, __shfl_xor_sync(0xffffffffu, mx, o));
    float sum = 0.f;
    for (int k = lane; k < NRQ; k += 32) { float e = __expf(p[k] - mx); p[k] = e; sum += e; }
    for (int o = 16; o; o >>= 1) sum += __shfl_xor_sync(0xffffffffu, sum, o);
    float inv = 1.f / sum;
    for (int k = lane; k < NRQ; k += 32) p[k] *= inv;
}

// ------------------------- ctx = attn @ V -----------------------------------
__global__ void ctx_kernel()
{
    int idx = blockIdx.x * blockDim.x + threadIdx.x;
    if (idx >= ROWS * DIM) return;
    int col = idx & 255;
    int row = idx >> 8;             // n*NRQ + q
    int n = row / NRQ, q = row % NRQ;
    int h = col >> 5;
    const float* ap = g_scores + ((size_t)(n * NHD + h) * NRQ + q) * NRQ;
    float acc = 0.f;
    for (int k = 0; k < NRQ; k++)
        acc += ap[k] * g_vp[(size_t)(n * NRQ + k) * DIM + col];
    g_ctx[idx] = acc;
}

// ------------------------- LayerNorm rows of 256 ----------------------------
__global__ void ln_kernel(const float* __restrict__ x, const float* __restrict__ res,
                          const float* __restrict__ mask, float* __restrict__ out, int relu)
{
    int row = blockIdx.x;
    int c = threadIdx.x;
    size_t base = (size_t)row * DIM;
    float v = x[base + c];
    if (res) v += res[base + c];
    float s = v, q = v * v;
    for (int o = 16; o; o >>= 1) {
        s += __shfl_xor_sync(0xffffffffu, s, o);
        q += __shfl_xor_sync(0xffffffffu, q, o);
    }
    __shared__ float ss[8], sq[8];
    int w = c >> 5, lane = c & 31;
    if (lane == 0) { ss[w] = s; sq[w] = q; }
    __syncthreads();
    float tot = 0.f, totq = 0.f;
#pragma unroll
    for (int i = 0; i < 8; i++) { tot += ss[i]; totq += sq[i]; }
    float mean = tot * (1.f / DIM);
    float var = totq * (1.f / DIM) - mean * mean;
    float y = (v - mean) * rsqrtf(var + 1e-5f);
    if (relu) y = fmaxf(y, 0.f);
    if (mask) y *= mask[row];
    out[base + c] = y;
}

// ------------------------- DynamicConv per instance -------------------------
__global__ __launch_bounds__(256) void dynconv_kernel(const float* __restrict__ roi)
{
    extern __shared__ float sm[];
    float* fsm  = sm;                 // 12544
    float* psm  = sm + 12544;         // 16384
    float* f1sm = psm + 16384;        // 3136
    int n = blockIdx.x, tid = threadIdx.x;

    for (int i = tid; i < SS * DIM; i += 256) {
        int s = i >> 8, d = i & 255;
        fsm[i] = roi[((size_t)s * ROWS + n) * DIM + d];
    }
    const float* pr = g_params + (size_t)n * (2 * DIM * DDI);
    for (int i = tid; i < DIM * DDI; i += 256) psm[i] = pr[i];
    __syncthreads();

    int e = tid & 63, sb = tid >> 6;
    for (int s = sb; s < SS; s += 4) {
        float acc = 0.f;
        const float* fr = fsm + s * DIM;
#pragma unroll 8
        for (int d = 0; d < DIM; d++) acc += fr[d] * psm[d * DDI + e];
        f1sm[s * DDI + e] = acc;
    }
    __syncthreads();

    int wid = tid >> 5, lane = tid & 31;
    for (int s = wid; s < SS; s += 8) {
        float a = f1sm[s * DDI + lane], b = f1sm[s * DDI + 32 + lane];
        float sum = a + b, ssq = a * a + b * b;
        for (int o = 16; o; o >>= 1) {
            sum += __shfl_xor_sync(0xffffffffu, sum, o);
            ssq += __shfl_xor_sync(0xffffffffu, ssq, o);
        }
        float mean = sum * (1.f / 64.f);
        float var = ssq * (1.f / 64.f) - mean * mean;
        float inv = rsqrtf(var + 1e-5f);
        f1sm[s * DDI + lane]      = fmaxf((a - mean) * inv, 0.f);
        f1sm[s * DDI + 32 + lane] = fmaxf((b - mean) * inv, 0.f);
    }
    for (int i = tid; i < DIM * DDI; i += 256) psm[i] = pr[DIM * DDI + i];
    __syncthreads();

    for (int s = 0; s < SS; s++) {
        float acc = 0.f;
#pragma unroll 8
        for (int ee = 0; ee < DDI; ee++) acc += f1sm[s * DDI + ee] * psm[ee * DIM + tid];
        fsm[s * DIM + tid] = acc;
    }
    __syncthreads();

    for (int s = wid; s < SS; s += 8) {
        float vals[8];
        float sum = 0.f, ssq = 0.f;
#pragma unroll
        for (int u = 0; u < 8; u++) {
            float v = fsm[s * DIM + lane + u * 32];
            vals[u] = v; sum += v; ssq += v * v;
        }
        for (int o = 16; o; o >>= 1) {
            sum += __shfl_xor_sync(0xffffffffu, sum, o);
            ssq += __shfl_xor_sync(0xffffffffu, ssq, o);
        }
        float mean = sum * (1.f / DIM);
        float var = ssq * (1.f / DIM) - mean * mean;
        float inv = rsqrtf(var + 1e-5f);
#pragma unroll
        for (int u = 0; u < 8; u++) {
            float y = fmaxf((vals[u] - mean) * inv, 0.f);
            g_f2[(size_t)n * (SS * DIM) + s * DIM + lane + u * 32] = y;
        }
    }
}

// ------------------------- host launch --------------------------------------
template <typename T>
static float* sym(T& s) { void* p = nullptr; cudaGetSymbolAddress(&p, s); return (float*)p; }

#define GEMM_SMEM 65536

static void launch_gemm(const float* A, const float* B, const float* bias, float* C,
                        int M, int N, int K, int lda, int ldb, int relu, int splitS)
{
    static bool attr_set = false;
    if (!attr_set) {
        cudaFuncSetAttribute(gemm_tf32, cudaFuncAttributeMaxDynamicSharedMemorySize, GEMM_SMEM);
        attr_set = true;
    }
    dim3 g(cdiv(N, BN), cdiv(M, BM), splitS);
    gemm_tf32<<<g, 256, GEMM_SMEM>>>(A, B, bias, C, M, N, K / splitS, lda, ldb, relu);
}

extern "C" void kernel_launch(void* const* d_in, const int* in_sizes, int n_in,
                              void* d_out, int out_size)
{
    const float* bboxes   = (const float*)d_in[0];
    const float* pro      = (const float*)d_in[1];
    const float* roi      = (const float*)d_in[2];
    const float* query    = (const float*)d_in[3];
    const float* mask     = (const float*)d_in[4];
    const float* w_qkv    = (const float*)d_in[5];
    const float* b_qkv    = (const float*)d_in[6];
    const float* w_attn   = (const float*)d_in[7];
    const float* b_attn   = (const float*)d_in[8];
    const float* w_dyn    = (const float*)d_in[9];
    const float* b_dyn    = (const float*)d_in[10];
    const float* w_dyno   = (const float*)d_in[11];
    const float* b_dyno   = (const float*)d_in[12];
    const float* w_ff1    = (const float*)d_in[13];
    const float* b_ff1    = (const float*)d_in[14];
    const float* w_ff2    = (const float*)d_in[15];
    const float* b_ff2    = (const float*)d_in[16];
    const float* w_cls    = (const float*)d_in[17];
    const float* w_logits = (const float*)d_in[18];
    const float* b_logits = (const float*)d_in[19];
    float* out = (float*)d_out;

    float* p_qk    = sym(g_qk);
    float* p_qkp   = sym(g_qkp);
    float* p_vp    = sym(g_vp);
    float* p_ctx   = sym(g_ctx);
    float* p_tgt2  = sym(g_tgt2);
    float* p_pf1   = sym(g_pf1);
    float* p_params= sym(g_params);
    float* p_f2    = sym(g_f2);
    float* p_dynr  = sym(g_dynraw);
    float* p_pf2   = sym(g_pf2);
    float* p_pfB   = sym(g_pfB);
    float* p_ffh   = sym(g_ffh);
    float* p_t2    = sym(g_t2);
    float* p_fc    = sym(g_fc);
    float* p_g1    = sym(g_g1);
    float* p_clsf  = sym(g_clsf);

    // 1. IoU relation mask
    iou_mask_kernel<<<cdiv(NB * NRQ * NRQ, 256), 256>>>(bboxes, mask);
    // 2. qk = pro + query
    qkadd_kernel<<<cdiv(ROWS * DIM, 256), 256>>>(pro, query);
    // 3. q,k projection: [2400,512]
    launch_gemm(p_qk, w_qkv, b_qkv, p_qkp, ROWS, 512, DIM, DIM, DIM, 0, 1);
    // 4. v projection from pro_features
    launch_gemm(pro, w_qkv + 512 * DIM, b_qkv + 512, p_vp, ROWS, DIM, DIM, DIM, DIM, 0, 1);
    // 5-7. attention
    {
        dim3 g(cdiv(NRQ, 32), NHD, NB);
        scores_kernel<<<g, 256>>>();
    }
    softmax_kernel<<<cdiv(NB * NHD * NRQ, 8), 256>>>();
    ctx_kernel<<<cdiv(ROWS * DIM, 256), 256>>>();
    // 8. out proj
    launch_gemm(p_ctx, w_attn, b_attn, p_tgt2, ROWS, DIM, DIM, DIM, DIM, 0, 1);
    // 9. norm1 + mask
    ln_kernel<<<ROWS, 256>>>(p_tgt2, pro, mask, p_pf1, 0);
    // 10. dyn params GEMM [2400, 32768]
    launch_gemm(p_pf1, w_dyn, b_dyn, p_params, ROWS, 2 * DIM * DDI, DIM, DIM, DIM, 0, 1);
    // 11. per-instance dynamic conv
    {
        int smem = (SS * DIM + DIM * DDI + SS * DDI) * 4;  // 128256 B
        cudaFuncSetAttribute(dynconv_kernel, cudaFuncAttributeMaxDynamicSharedMemorySize, smem);
        dynconv_kernel<<<ROWS, 256, smem>>>(roi);
    }
    // 12. out_layer GEMM: [2400,256], K=12544, split-K=8 (g_params free -> scratch)
    launch_gemm(p_f2, w_dyno, nullptr, p_params, ROWS, DIM, SS * DIM, SS * DIM, SS * DIM, 0, 8);
    splitk_reduce<<<cdiv(ROWS * DIM, 256), 256>>>(p_params, b_dyno, p_dynr, ROWS * DIM, DIM, 8);
    // 13. pf2 = relu(ln(dynraw))
    ln_kernel<<<ROWS, 256>>>(p_dynr, nullptr, nullptr, p_pf2, 1);
    // 14. norm2: pfB = ln(pf1 + pf2)
    ln_kernel<<<ROWS, 256>>>(p_pf2, p_pf1, nullptr, p_pfB, 0);
    // 15. FFN 1 (relu)
    launch_gemm(p_pfB, w_ff1, b_ff1, p_ffh, ROWS, FFD, DIM, DIM, DIM, 1, 1);
    // 16. FFN 2, split-K=4
    launch_gemm(p_ffh, w_ff2, nullptr, p_params, ROWS, DIM, FFD, FFD, FFD, 0, 4);
    splitk_reduce<<<cdiv(ROWS * DIM, 256), 256>>>(p_params, b_ff2, p_t2, ROWS * DIM, DIM, 4);
    // 17. norm3 + mask -> fc
    ln_kernel<<<ROWS, 256>>>(p_t2, p_pfB, mask, p_fc, 0);
    // 18. cls tower linear (no bias)
    launch_gemm(p_fc, w_cls, nullptr, p_g1, ROWS, DIM, DIM, DIM, DIM, 0, 1);
    // 19. cls_f = relu(ln(g1))
    ln_kernel<<<ROWS, 256>>>(p_g1, nullptr, nullptr, p_clsf, 1);
    // 20. logits -> d_out [2400, 80]
    launch_gemm(p_clsf, w_logits, b_logits, out, ROWS, NCLS, DIM, DIM, DIM, 0, 1);
}

// round 11
// speedup vs baseline: 2.8104x; 1.0411x over previous
#include <cuda_runtime.h>
#include <cstdint>
#include <cstddef>

#define NB   8
#define NRQ  300
#define DIM  256
#define NHD  8
#define HDM  32
#define SS   49
#define DDI  64
#define FFD  2048
#define NCLS 80
#define ROWS 2400   // NB*NRQ

// ------------------------- scratch (device globals) -------------------------
__device__ float g_qk   [ROWS * DIM];
__device__ float g_qkp  [ROWS * 512];                 // q proj | k proj
__device__ float g_vp   [ROWS * DIM];
__device__ float g_mflag[NB * NRQ * NRQ];             // 1 = masked
__device__ float g_scores[(size_t)NB * NHD * NRQ * NRQ];
__device__ float g_ctx  [ROWS * DIM];
__device__ float g_tgt2 [ROWS * DIM];
__device__ float g_pf1  [ROWS * DIM];
__device__ float g_params[(size_t)ROWS * 2 * DIM * DDI];   // 314 MB (also split-K scratch)
__device__ float g_f2   [(size_t)ROWS * SS * DIM];         // 120 MB
__device__ float g_dynraw[ROWS * DIM];
__device__ float g_pf2  [ROWS * DIM];
__device__ float g_pfB  [ROWS * DIM];
__device__ float g_ffh  [(size_t)ROWS * FFD];
__device__ float g_t2   [ROWS * DIM];
__device__ float g_fc   [ROWS * DIM];
__device__ float g_g1   [ROWS * DIM];
__device__ float g_clsf [ROWS * DIM];

static inline int cdiv(int a, int b) { return (a + b - 1) / b; }

// ------------------------- TF32 tensor-core GEMM ----------------------------
// C = A * B^T (+bias) (optional relu). A[M,K] rm (lda), B[N,K] rm (ldb).
// kChunk % 32 == 0. blockIdx.z = split-K slice (A,B advance z*kChunk; C by z*M*N).
// CTA tile 128x128x32, 8 warps (2m x 4n), warp tile 64x32, m16n8k8 tf32.
// Smem in FRAGMENT ORDER (tf32-converted), LDS.128/STS.128 conflict-free.
#define BM 128
#define BN 128
#define BK 32

__device__ __forceinline__ uint32_t f2tf32(float f) {
    uint32_t u;
    asm("cvt.rna.tf32.f32 %0, %1;" : "=r"(u) : "f"(f));
    return u;
}

__global__ __launch_bounds__(256, 2) void gemm_tf32(
    const float* __restrict__ A, const float* __restrict__ B,
    const float* __restrict__ bias, float* __restrict__ C,
    int M, int N, int kChunk, int lda, int ldb, int relu)
{
    extern __shared__ uint32_t dynsm[];           // [2][8192]: A at +0, B at +4096
    int tid = threadIdx.x;
    int lane = tid & 31;
    int wrp = tid >> 5;
    int gp = lane >> 2, tg = lane & 3;
    int bm = blockIdx.y * BM, bn = blockIdx.x * BN;

    // split-K slice offsets
    A += (size_t)blockIdx.z * kChunk;
    B += (size_t)blockIdx.z * kChunk;
    C += (size_t)blockIdx.z * M * N;

    int wm = wrp & 1, wn = wrp >> 1;

    float c[4][4][4];
#pragma unroll
    for (int mi = 0; mi < 4; mi++)
#pragma unroll
        for (int ni = 0; ni < 4; ni++)
#pragma unroll
            for (int r = 0; r < 4; r++) c[mi][ni][r] = 0.f;

    // ---- loader precompute: each warp owns chunks {wrp, wrp+8, wrp+16, wrp+24}
    const float* aptr[4]; bool aok0[4], aok1[4]; int stsoff[4];
    const float* bptr[4]; bool bok0[4], bok1[4];
#pragma unroll
    for (int i = 0; i < 4; i++) {
        int cc = wrp + 8 * i;
        stsoff[i] = (cc << 7) + (lane << 2);
        {
            int ks = cc >> 3, wmc = (cc >> 2) & 1, mi = cc & 3;
            int row = wmc * 64 + mi * 16 + gp;
            int kk = ks * 8 + tg;
            aptr[i] = A + (size_t)(bm + row) * lda + kk;
            aok0[i] = (bm + row) < M;
            aok1[i] = (bm + row + 8) < M;
        }
        {
            int ks = cc >> 3, wnc = (cc & 7) >> 1, h = cc & 1;
            int col = wnc * 32 + h * 16 + gp;
            int kk = ks * 8 + tg;
            bptr[i] = B + (size_t)(bn + col) * ldb + kk;
            bok0[i] = (bn + col) < N;
            bok1[i] = (bn + col + 8) < N;
        }
    }

    int nk = kChunk / BK;
    float4 ra[4], rb[4];

    auto stsA = [&](int s) {
#pragma unroll
        for (int i = 0; i < 4; i++) {
            uint4 u;
            u.x = f2tf32(ra[i].x); u.y = f2tf32(ra[i].y);
            u.z = f2tf32(ra[i].z); u.w = f2tf32(ra[i].w);
            *(uint4*)&dynsm[s * 8192 + stsoff[i]] = u;
        }
    };
    auto stsB = [&](int s) {
#pragma unroll
        for (int i = 0; i < 4; i++) {
            uint4 u;
            u.x = f2tf32(rb[i].x); u.y = f2tf32(rb[i].y);
            u.z = f2tf32(rb[i].z); u.w = f2tf32(rb[i].w);
            *(uint4*)&dynsm[s * 8192 + 4096 + stsoff[i]] = u;
        }
    };
    auto ldgA = [&]() {
#pragma unroll
        for (int i = 0; i < 4; i++) {
            const float* p = aptr[i];
            ra[i].x = aok0[i] ? p[0] : 0.f;
            ra[i].y = aok1[i] ? p[(size_t)8 * lda] : 0.f;
            ra[i].z = aok0[i] ? p[4] : 0.f;
            ra[i].w = aok1[i] ? p[(size_t)8 * lda + 4] : 0.f;
            aptr[i] += BK;
        }
    };
    auto ldgB = [&]() {
#pragma unroll
        for (int i = 0; i < 4; i++) {
            const float* p = bptr[i];
            rb[i].x = bok0[i] ? p[0] : 0.f;
            rb[i].y = bok0[i] ? p[4] : 0.f;
            rb[i].z = bok1[i] ? p[(size_t)8 * ldb] : 0.f;
            rb[i].w = bok1[i] ? p[(size_t)8 * ldb + 4] : 0.f;
            bptr[i] += BK;
        }
    };
    auto compute = [&](int s, int ks) {
        const uint32_t* smA = dynsm + s * 8192;
        const uint32_t* smB = smA + 4096;
        uint4 av[4];
#pragma unroll
        for (int mi = 0; mi < 4; mi++)
            av[mi] = *(const uint4*)&smA[((ks * 8 + wm * 4 + mi) << 7) + (lane << 2)];
        uint4 bv0 = *(const uint4*)&smB[((ks * 8 + wn * 2 + 0) << 7) + (lane << 2)];
        uint4 bv1 = *(const uint4*)&smB[((ks * 8 + wn * 2 + 1) << 7) + (lane << 2)];
        uint32_t bf[4][2] = {{bv0.x, bv0.y}, {bv0.z, bv0.w}, {bv1.x, bv1.y}, {bv1.z, bv1.w}};
#pragma unroll
        for (int mi = 0; mi < 4; mi++)
#pragma unroll
            for (int ni = 0; ni < 4; ni++) {
                asm volatile(
                    "mma.sync.aligned.m16n8k8.row.col.f32.tf32.tf32.f32 "
                    "{%0,%1,%2,%3}, {%4,%5,%6,%7}, {%8,%9}, {%0,%1,%2,%3};"
                    : "+f"(c[mi][ni][0]), "+f"(c[mi][ni][1]),
                      "+f"(c[mi][ni][2]), "+f"(c[mi][ni][3])
                    : "r"(av[mi].x), "r"(av[mi].y), "r"(av[mi].z), "r"(av[mi].w),
                      "r"(bf[ni][0]), "r"(bf[ni][1]));
            }
    };

    // prologue: tile 0 -> stage 0
    ldgA(); ldgB();
    stsA(0); stsB(0);
    __syncthreads();

    int s = 0;
    for (int kt = 0; kt < nk; kt++) {
        bool nxt = (kt + 1) < nk;
        if (nxt) ldgA();
        compute(s, 0);
        compute(s, 1);
        if (nxt) { stsA(s ^ 1); ldgB(); }
        compute(s, 2);
        compute(s, 3);
        if (nxt) stsB(s ^ 1);
        __syncthreads();
        s ^= 1;
    }

    // --- epilogue ---
#pragma unroll
    for (int mi = 0; mi < 4; mi++) {
        int r0 = bm + wm * 64 + mi * 16 + gp;
#pragma unroll
        for (int ni = 0; ni < 4; ni++) {
            int col = bn + wn * 32 + ni * 8 + 2 * tg;
            if (col >= N) continue;
            float b0 = bias ? bias[col] : 0.f;
            float b1 = bias ? bias[col + 1] : 0.f;
            if (r0 < M) {
                float v0 = c[mi][ni][0] + b0;
                float v1 = c[mi][ni][1] + b1;
                if (relu) { v0 = fmaxf(v0, 0.f); v1 = fmaxf(v1, 0.f); }
                *(float2*)(C + (size_t)r0 * N + col) = make_float2(v0, v1);
            }
            if (r0 + 8 < M) {
                float v2 = c[mi][ni][2] + b0;
                float v3 = c[mi][ni][3] + b1;
                if (relu) { v2 = fmaxf(v2, 0.f); v3 = fmaxf(v3, 0.f); }
                *(float2*)(C + (size_t)(r0 + 8) * N + col) = make_float2(v2, v3);
            }
        }
    }
}

// split-K reduce: out[i] = sum_s part[s*MN+i] (+ bias[i%N]); fixed order => deterministic
__global__ void splitk_reduce(const float* __restrict__ part, const float* __restrict__ bias,
                              float* __restrict__ out, int MN, int N, int S)
{
    int i = blockIdx.x * 256 + threadIdx.x;
    if (i >= MN) return;
    float acc = bias ? bias[i % N] : 0.f;
    for (int si = 0; si < S; si++) acc += part[(size_t)si * MN + i];
    out[i] = acc;
}

// ------------------------- IoU relation mask --------------------------------
__global__ void iou_mask_kernel(const float* __restrict__ bboxes,
                                const float* __restrict__ mask)
{
    int idx = blockIdx.x * blockDim.x + threadIdx.x;
    if (idx >= NB * NRQ * NRQ) return;
    int j = idx % NRQ;
    int i = (idx / NRQ) % NRQ;
    int n = idx / (NRQ * NRQ);
    const float* bi = bboxes + (size_t)(n * NRQ + i) * 4;
    const float* bj = bboxes + (size_t)(n * NRQ + j) * 4;
    float ax0 = bi[0], ay0 = bi[1], ax1 = bi[2], ay1 = bi[3];
    float bx0 = bj[0], by0 = bj[1], bx1 = bj[2], by1 = bj[3];
    float areaA = (ax1 - ax0) * (ay1 - ay0);
    float areaB = (bx1 - bx0) * (by1 - by0);
    float lx = fmaxf(ax0, bx0), ly = fmaxf(ay0, by0);
    float rx = fminf(ax1, bx1), ry = fminf(ay1, by1);
    float w = fmaxf(rx - lx, 0.f), h = fmaxf(ry - ly, 0.f);
    float inter = w * h;
    float uni = areaA + areaB - inter;
    float iou = inter / fmaxf(uni, 1e-9f);
    float mi = mask[n * NRQ + i], mj = mask[n * NRQ + j];
    bool masked = ((iou < 0.5f) && mi > 0.f && mj > 0.f) || (i == j && mi == 0.f);
    g_mflag[idx] = masked ? 1.f : 0.f;
}

// ------------------------- qk = pro + query ---------------------------------
__global__ void qkadd_kernel(const float* __restrict__ pro, const float* __restrict__ query)
{
    int idx = blockIdx.x * blockDim.x + threadIdx.x;
    if (idx >= ROWS * DIM) return;
    g_qk[idx] = pro[idx] + query[idx];
}

// ------------------------- attention scores ---------------------------------
__global__ void scores_kernel()
{
    int n = blockIdx.z, h = blockIdx.y, qt = blockIdx.x * 32;
    __shared__ float Qs[32][32];
    __shared__ float Ks[32][33];
    int tid = threadIdx.x;
    int r = tid / 32, c = tid % 32;
    for (int rr = r; rr < 32; rr += 8) {
        int q = qt + rr;
        Qs[rr][c] = (q < NRQ) ? g_qkp[(size_t)(n * NRQ + q) * 512 + h * 32 + c] : 0.f;
    }
    const float scale = 0.17677669529663687f;  // 1/sqrt(32)
    for (int kt = 0; kt < NRQ; kt += 32) {
        __syncthreads();
        for (int rr = r; rr < 32; rr += 8) {
            int k = kt + rr;
            Ks[rr][c] = (k < NRQ) ? g_qkp[(size_t)(n * NRQ + k) * 512 + 256 + h * 32 + c] : 0.f;
        }
        __syncthreads();
        int kk = tid % 32, qr0 = tid / 32;
        float acc[4] = {0.f, 0.f, 0.f, 0.f};
#pragma unroll
        for (int d = 0; d < 32; d++) {
            float kv = Ks[kk][d];
#pragma unroll
            for (int u = 0; u < 4; u++) acc[u] += Qs[qr0 + u * 8][d] * kv;
        }
#pragma unroll
        for (int u = 0; u < 4; u++) {
            int q = qt + qr0 + u * 8;
            int k = kt + kk;
            if (q < NRQ && k < NRQ) {
                float flag = g_mflag[(size_t)(n * NRQ + q) * NRQ + k];
                size_t off = ((size_t)(n * NHD + h) * NRQ + q) * NRQ + k;
                g_scores[off] = (flag > 0.f) ? -1e9f : acc[u] * scale;
            }
        }
    }
}

// ------------------------- row softmax (one warp per row) -------------------
__global__ void softmax_kernel()
{
    int row = blockIdx.x * 8 + threadIdx.x / 32;
    int lane = threadIdx.x % 32;
    if (row >= NB * NHD * NRQ) return;
    float* p = g_scores + (size_t)row * NRQ;
    float mx = -1e30f;
    for (int k = lane; k < NRQ; k += 32) mx = fmaxf(mx, p[k]);
    for (int o = 16; o; o >>= 1) mx = fmaxf(mx, __shfl_xor_sync(0xffffffffu, mx, o));
    float sum = 0.f;
    for (int k = lane; k < NRQ; k += 32) { float e = __expf(p[k] - mx); p[k] = e; sum += e; }
    for (int o = 16; o; o >>= 1) sum += __shfl_xor_sync(0xffffffffu, sum, o);
    float inv = 1.f / sum;
    for (int k = lane; k < NRQ; k += 32) p[k] *= inv;
}

// ------------------------- ctx = attn @ V -----------------------------------
__global__ void ctx_kernel()
{
    int idx = blockIdx.x * blockDim.x + threadIdx.x;
    if (idx >= ROWS * DIM) return;
    int col = idx & 255;
    int row = idx >> 8;             // n*NRQ + q
    int n = row / NRQ, q = row % NRQ;
    int h = col >> 5;
    const float* ap = g_scores + ((size_t)(n * NHD + h) * NRQ + q) * NRQ;
    float acc = 0.f;
    for (int k = 0; k < NRQ; k++)
        acc += ap[k] * g_vp[(size_t)(n * NRQ + k) * DIM + col];
    g_ctx[idx] = acc;
}

// ------------------------- LayerNorm rows of 256 ----------------------------
__global__ void ln_kernel(const float* __restrict__ x, const float* __restrict__ res,
                          const float* __restrict__ mask, float* __restrict__ out, int relu)
{
    int row = blockIdx.x;
    int c = threadIdx.x;
    size_t base = (size_t)row * DIM;
    float v = x[base + c];
    if (res) v += res[base + c];
    float s = v, q = v * v;
    for (int o = 16; o; o >>= 1) {
        s += __shfl_xor_sync(0xffffffffu, s, o);
        q += __shfl_xor_sync(0xffffffffu, q, o);
    }
    __shared__ float ss[8], sq[8];
    int w = c >> 5, lane = c & 31;
    if (lane == 0) { ss[w] = s; sq[w] = q; }
    __syncthreads();
    float tot = 0.f, totq = 0.f;
#pragma unroll
    for (int i = 0; i < 8; i++) { tot += ss[i]; totq += sq[i]; }
    float mean = tot * (1.f / DIM);
    float var = totq * (1.f / DIM) - mean * mean;
    float y = (v - mean) * rsqrtf(var + 1e-5f);
    if (relu) y = fmaxf(y, 0.f);
    if (mask) y *= mask[row];
    out[base + c] = y;
}

// ------------------------- DynamicConv per instance -------------------------
__global__ __launch_bounds__(256) void dynconv_kernel(const float* __restrict__ roi)
{
    extern __shared__ float sm[];
    float* fsm  = sm;                 // 12544
    float* psm  = sm + 12544;         // 16384
    float* f1sm = psm + 16384;        // 3136
    int n = blockIdx.x, tid = threadIdx.x;

    for (int i = tid; i < SS * DIM; i += 256) {
        int s = i >> 8, d = i & 255;
        fsm[i] = roi[((size_t)s * ROWS + n) * DIM + d];
    }
    const float* pr = g_params + (size_t)n * (2 * DIM * DDI);
    for (int i = tid; i < DIM * DDI; i += 256) psm[i] = pr[i];
    __syncthreads();

    int e = tid & 63, sb = tid >> 6;
    for (int s = sb; s < SS; s += 4) {
        float acc = 0.f;
        const float* fr = fsm + s * DIM;
#pragma unroll 8
        for (int d = 0; d < DIM; d++) acc += fr[d] * psm[d * DDI + e];
        f1sm[s * DDI + e] = acc;
    }
    __syncthreads();

    int wid = tid >> 5, lane = tid & 31;
    for (int s = wid; s < SS; s += 8) {
        float a = f1sm[s * DDI + lane], b = f1sm[s * DDI + 32 + lane];
        float sum = a + b, ssq = a * a + b * b;
        for (int o = 16; o; o >>= 1) {
            sum += __shfl_xor_sync(0xffffffffu, sum, o);
            ssq += __shfl_xor_sync(0xffffffffu, ssq, o);
        }
        float mean = sum * (1.f / 64.f);
        float var = ssq * (1.f / 64.f) - mean * mean;
        float inv = rsqrtf(var + 1e-5f);
        f1sm[s * DDI + lane]      = fmaxf((a - mean) * inv, 0.f);
        f1sm[s * DDI + 32 + lane] = fmaxf((b - mean) * inv, 0.f);
    }
    for (int i = tid; i < DIM * DDI; i += 256) psm[i] = pr[DIM * DDI + i];
    __syncthreads();

    for (int s = 0; s < SS; s++) {
        float acc = 0.f;
#pragma unroll 8
        for (int ee = 0; ee < DDI; ee++) acc += f1sm[s * DDI + ee] * psm[ee * DIM + tid];
        fsm[s * DIM + tid] = acc;
    }
    __syncthreads();

    for (int s = wid; s < SS; s += 8) {
        float vals[8];
        float sum = 0.f, ssq = 0.f;
#pragma unroll
        for (int u = 0; u < 8; u++) {
            float v = fsm[s * DIM + lane + u * 32];
            vals[u] = v; sum += v; ssq += v * v;
        }
        for (int o = 16; o; o >>= 1) {
            sum += __shfl_xor_sync(0xffffffffu, sum, o);
            ssq += __shfl_xor_sync(0xffffffffu, ssq, o);
        }
        float mean = sum * (1.f / DIM);
        float var = ssq * (1.f / DIM) - mean * mean;
        float inv = rsqrtf(var + 1e-5f);
#pragma unroll
        for (int u = 0; u < 8; u++) {
            float y = fmaxf((vals[u] - mean) * inv, 0.f);
            g_f2[(size_t)n * (SS * DIM) + s * DIM + lane + u * 32] = y;
        }
    }
}

// ------------------------- host launch --------------------------------------
template <typename T>
static float* sym(T& s) { void* p = nullptr; cudaGetSymbolAddress(&p, s); return (float*)p; }

#define GEMM_SMEM 65536

static void launch_gemm(const float* A, const float* B, const float* bias, float* C,
                        int M, int N, int K, int lda, int ldb, int relu, int splitS)
{
    static bool attr_set = false;
    if (!attr_set) {
        cudaFuncSetAttribute(gemm_tf32, cudaFuncAttributeMaxDynamicSharedMemorySize, GEMM_SMEM);
        attr_set = true;
    }
    dim3 g(cdiv(N, BN), cdiv(M, BM), splitS);
    gemm_tf32<<<g, 256, GEMM_SMEM>>>(A, B, bias, C, M, N, K / splitS, lda, ldb, relu);
}

extern "C" void kernel_launch(void* const* d_in, const int* in_sizes, int n_in,
                              void* d_out, int out_size)
{
    const float* bboxes   = (const float*)d_in[0];
    const float* pro      = (const float*)d_in[1];
    const float* roi      = (const float*)d_in[2];
    const float* query    = (const float*)d_in[3];
    const float* mask     = (const float*)d_in[4];
    const float* w_qkv    = (const float*)d_in[5];
    const float* b_qkv    = (const float*)d_in[6];
    const float* w_attn   = (const float*)d_in[7];
    const float* b_attn   = (const float*)d_in[8];
    const float* w_dyn    = (const float*)d_in[9];
    const float* b_dyn    = (const float*)d_in[10];
    const float* w_dyno   = (const float*)d_in[11];
    const float* b_dyno   = (const float*)d_in[12];
    const float* w_ff1    = (const float*)d_in[13];
    const float* b_ff1    = (const float*)d_in[14];
    const float* w_ff2    = (const float*)d_in[15];
    const float* b_ff2    = (const float*)d_in[16];
    const float* w_cls    = (const float*)d_in[17];
    const float* w_logits = (const float*)d_in[18];
    const float* b_logits = (const float*)d_in[19];
    float* out = (float*)d_out;

    float* p_qk    = sym(g_qk);
    float* p_qkp   = sym(g_qkp);
    float* p_vp    = sym(g_vp);
    float* p_ctx   = sym(g_ctx);
    float* p_tgt2  = sym(g_tgt2);
    float* p_pf1   = sym(g_pf1);
    float* p_params= sym(g_params);
    float* p_f2    = sym(g_f2);
    float* p_dynr  = sym(g_dynraw);
    float* p_pf2   = sym(g_pf2);
    float* p_pfB   = sym(g_pfB);
    float* p_ffh   = sym(g_ffh);
    float* p_t2    = sym(g_t2);
    float* p_fc    = sym(g_fc);
    float* p_g1    = sym(g_g1);
    float* p_clsf  = sym(g_clsf);

    // 1. IoU relation mask
    iou_mask_kernel<<<cdiv(NB * NRQ * NRQ, 256), 256>>>(bboxes, mask);
    // 2. qk = pro + query
    qkadd_kernel<<<cdiv(ROWS * DIM, 256), 256>>>(pro, query);
    // 3. q,k projection: [2400,512], split-K=2 (g_params free -> scratch)
    launch_gemm(p_qk, w_qkv, nullptr, p_params, ROWS, 512, DIM, DIM, DIM, 0, 2);
    splitk_reduce<<<cdiv(ROWS * 512, 256), 256>>>(p_params, b_qkv, p_qkp, ROWS * 512, 512, 2);
    // 4. v projection from pro_features, split-K=2 (use scratch past QK partials)
    {
        float* scr = p_params + 2 * ROWS * 512;
        launch_gemm(pro, w_qkv + 512 * DIM, nullptr, scr, ROWS, DIM, DIM, DIM, DIM, 0, 2);
        splitk_reduce<<<cdiv(ROWS * DIM, 256), 256>>>(scr, b_qkv + 512, p_vp, ROWS * DIM, DIM, 2);
    }
    // 5-7. attention
    {
        dim3 g(cdiv(NRQ, 32), NHD, NB);
        scores_kernel<<<g, 256>>>();
    }
    softmax_kernel<<<cdiv(NB * NHD * NRQ, 8), 256>>>();
    ctx_kernel<<<cdiv(ROWS * DIM, 256), 256>>>();
    // 8. out proj, split-K=2
    launch_gemm(p_ctx, w_attn, nullptr, p_params, ROWS, DIM, DIM, DIM, DIM, 0, 2);
    splitk_reduce<<<cdiv(ROWS * DIM, 256), 256>>>(p_params, b_attn, p_tgt2, ROWS * DIM, DIM, 2);
    // 9. norm1 + mask
    ln_kernel<<<ROWS, 256>>>(p_tgt2, pro, mask, p_pf1, 0);
    // 10. dyn params GEMM [2400, 32768] (full grid already)
    launch_gemm(p_pf1, w_dyn, b_dyn, p_params, ROWS, 2 * DIM * DDI, DIM, DIM, DIM, 0, 1);
    // 11. per-instance dynamic conv
    {
        int smem = (SS * DIM + DIM * DDI + SS * DDI) * 4;  // 128256 B
        cudaFuncSetAttribute(dynconv_kernel, cudaFuncAttributeMaxDynamicSharedMemorySize, smem);
        dynconv_kernel<<<ROWS, 256, smem>>>(roi);
    }
    // 12. out_layer GEMM: [2400,256], K=12544, split-K=8 (g_params free -> scratch)
    launch_gemm(p_f2, w_dyno, nullptr, p_params, ROWS, DIM, SS * DIM, SS * DIM, SS * DIM, 0, 8);
    splitk_reduce<<<cdiv(ROWS * DIM, 256), 256>>>(p_params, b_dyno, p_dynr, ROWS * DIM, DIM, 8);
    // 13. pf2 = relu(ln(dynraw))
    ln_kernel<<<ROWS, 256>>>(p_dynr, nullptr, nullptr, p_pf2, 1);
    // 14. norm2: pfB = ln(pf1 + pf2)
    ln_kernel<<<ROWS, 256>>>(p_pf2, p_pf1, nullptr, p_pfB, 0);
    // 15. FFN 1 (relu)
    launch_gemm(p_pfB, w_ff1, b_ff1, p_ffh, ROWS, FFD, DIM, DIM, DIM, 1, 1);
    // 16. FFN 2, split-K=4
    launch_gemm(p_ffh, w_ff2, nullptr, p_params, ROWS, DIM, FFD, FFD, FFD, 0, 4);
    splitk_reduce<<<cdiv(ROWS * DIM, 256), 256>>>(p_params, b_ff2, p_t2, ROWS * DIM, DIM, 4);
    // 17. norm3 + mask -> fc
    ln_kernel<<<ROWS, 256>>>(p_t2, p_pfB, mask, p_fc, 0);
    // 18. cls tower linear (no bias), split-K=2
    launch_gemm(p_fc, w_cls, nullptr, p_params, ROWS, DIM, DIM, DIM, DIM, 0, 2);
    splitk_reduce<<<cdiv(ROWS * DIM, 256), 256>>>(p_params, nullptr, p_g1, ROWS * DIM, DIM, 2);
    // 19. cls_f = relu(ln(g1))
    ln_kernel<<<ROWS, 256>>>(p_g1, nullptr, nullptr, p_clsf, 1);
    // 20. logits -> d_out [2400, 80], split-K=2
    launch_gemm(p_clsf, w_logits, nullptr, p_params, ROWS, NCLS, DIM, DIM, DIM, 0, 2);
    splitk_reduce<<<cdiv(ROWS * NCLS, 256), 256>>>(p_params, b_logits, out, ROWS * NCLS, NCLS, 2);
}

// round 14
// speedup vs baseline: 2.9888x; 1.0635x over previous
#include <cuda_runtime.h>
#include <cstdint>
#include <cstddef>

#define NB   8
#define NRQ  300
#define DIM  256
#define NHD  8
#define HDM  32
#define SS   49
#define DDI  64
#define FFD  2048
#define NCLS 80
#define ROWS 2400   // NB*NRQ

// ------------------------- scratch (device globals) -------------------------
__device__ float g_qk   [ROWS * DIM];
__device__ float g_qkp  [ROWS * 512];                 // q proj | k proj
__device__ float g_vp   [ROWS * DIM];
__device__ float g_mflag[NB * NRQ * NRQ];             // 1 = masked
__device__ float g_scores[(size_t)NB * NHD * NRQ * NRQ];
__device__ float g_ctx  [ROWS * DIM];
__device__ float g_tgt2 [ROWS * DIM];
__device__ float g_pf1  [ROWS * DIM];
__device__ float g_params[(size_t)ROWS * 2 * DIM * DDI];   // 314 MB (also split-K scratch)
__device__ float g_f2   [(size_t)ROWS * SS * DIM];         // 120 MB
__device__ float g_dynraw[ROWS * DIM];
__device__ float g_pf2  [ROWS * DIM];
__device__ float g_pfB  [ROWS * DIM];
__device__ float g_ffh  [(size_t)ROWS * FFD];
__device__ float g_t2   [ROWS * DIM];
__device__ float g_fc   [ROWS * DIM];
__device__ float g_g1   [ROWS * DIM];
__device__ float g_clsf [ROWS * DIM];

static inline int cdiv(int a, int b) { return (a + b - 1) / b; }

// ------------------------- TF32 tensor-core GEMM ----------------------------
// C = A * B^T (+bias) (optional relu). A[M,K] rm (lda), B[N,K] rm (ldb).
// kChunk % 32 == 0. blockIdx.z = split-K slice (A,B advance z*kChunk; C by z*M*N).
// CTA tile 128x128x32, 8 warps (2m x 4n), warp tile 64x32, m16n8k8 tf32.
// Smem in FRAGMENT ORDER (tf32-converted):
//   A chunk c = ks*8 + wm*4 + mi ; B chunk c = ks*8 + wn*2 + h (32 chunks each,
//   128 words, word = c*128 + lane*4 + r) -> LDS.128 / STS.128 conflict-free.
// No register staging: per ktile compute(s) then LDG->cvt->STS into s^1; the
// exposed latency is covered by the co-resident CTA (launch_bounds (256,2)).
#define BM 128
#define BN 128
#define BK 32

__device__ __forceinline__ uint32_t f2tf32(float f) {
    uint32_t u;
    asm("cvt.rna.tf32.f32 %0, %1;" : "=r"(u) : "f"(f));
    return u;
}

__global__ __launch_bounds__(256, 2) void gemm_tf32(
    const float* __restrict__ A, const float* __restrict__ B,
    const float* __restrict__ bias, float* __restrict__ C,
    int M, int N, int kChunk, int lda, int ldb, int relu)
{
    extern __shared__ uint32_t dynsm[];           // [2][8192]: A at +0, B at +4096
    int tid = threadIdx.x;
    int lane = tid & 31;
    int wrp = tid >> 5;
    int gp = lane >> 2, tg = lane & 3;
    int bm = blockIdx.y * BM, bn = blockIdx.x * BN;

    // split-K slice offsets
    A += (size_t)blockIdx.z * kChunk;
    B += (size_t)blockIdx.z * kChunk;
    C += (size_t)blockIdx.z * M * N;

    int wm = wrp & 1, wn = wrp >> 1;

    float c[4][4][4];
#pragma unroll
    for (int mi = 0; mi < 4; mi++)
#pragma unroll
        for (int ni = 0; ni < 4; ni++)
#pragma unroll
            for (int r = 0; r < 4; r++) c[mi][ni][r] = 0.f;

    // Load one ktile (A+B) into stage s at k-offset koff. Each warp fills
    // chunks {wrp, wrp+8, wrp+16, wrp+24} of both tiles. All state transient.
    auto load_tiles = [&](int s, int koff) {
#pragma unroll
        for (int i = 0; i < 4; i++) {
            int cc = wrp + 8 * i;
            int ks = cc >> 3;
            int kk = ks * 8 + tg + koff;
            uint32_t soff = (uint32_t)(cc << 7) + (uint32_t)(lane << 2);
            // --- A chunk: c = ks*8 + wmc*4 + mi ---
            {
                int wmc = (cc >> 2) & 1, mi = cc & 3;
                int row = bm + wmc * 64 + mi * 16 + gp;
                const float* p = A + (size_t)row * lda + kk;
                bool ok0 = row < M, ok1 = (row + 8) < M;
                float x0 = ok0 ? p[0] : 0.f;
                float x1 = ok1 ? p[(size_t)8 * lda] : 0.f;
                float x2 = ok0 ? p[4] : 0.f;
                float x3 = ok1 ? p[(size_t)8 * lda + 4] : 0.f;
                uint4 u;
                u.x = f2tf32(x0); u.y = f2tf32(x1); u.z = f2tf32(x2); u.w = f2tf32(x3);
                *(uint4*)&dynsm[s * 8192 + soff] = u;
            }
            // --- B chunk: c = ks*8 + wnc*2 + h ---
            {
                int wnc = (cc & 7) >> 1, h = cc & 1;
                int col = bn + wnc * 32 + h * 16 + gp;
                const float* p = B + (size_t)col * ldb + kk;
                bool ok0 = col < N, ok1 = (col + 8) < N;
                float x0 = ok0 ? p[0] : 0.f;
                float x1 = ok0 ? p[4] : 0.f;
                float x2 = ok1 ? p[(size_t)8 * ldb] : 0.f;
                float x3 = ok1 ? p[(size_t)8 * ldb + 4] : 0.f;
                uint4 u;
                u.x = f2tf32(x0); u.y = f2tf32(x1); u.z = f2tf32(x2); u.w = f2tf32(x3);
                *(uint4*)&dynsm[s * 8192 + 4096 + soff] = u;
            }
        }
    };

    auto compute = [&](int s, int ks) {
        const uint32_t* smA = dynsm + s * 8192;
        const uint32_t* smB = smA + 4096;
        uint4 av[4];
#pragma unroll
        for (int mi = 0; mi < 4; mi++)
            av[mi] = *(const uint4*)&smA[((ks * 8 + wm * 4 + mi) << 7) + (lane << 2)];
        uint4 bv0 = *(const uint4*)&smB[((ks * 8 + wn * 2 + 0) << 7) + (lane << 2)];
        uint4 bv1 = *(const uint4*)&smB[((ks * 8 + wn * 2 + 1) << 7) + (lane << 2)];
        uint32_t bf[4][2] = {{bv0.x, bv0.y}, {bv0.z, bv0.w}, {bv1.x, bv1.y}, {bv1.z, bv1.w}};
#pragma unroll
        for (int mi = 0; mi < 4; mi++)
#pragma unroll
            for (int ni = 0; ni < 4; ni++) {
                asm volatile(
                    "mma.sync.aligned.m16n8k8.row.col.f32.tf32.tf32.f32 "
                    "{%0,%1,%2,%3}, {%4,%5,%6,%7}, {%8,%9}, {%0,%1,%2,%3};"
                    : "+f"(c[mi][ni][0]), "+f"(c[mi][ni][1]),
                      "+f"(c[mi][ni][2]), "+f"(c[mi][ni][3])
                    : "r"(av[mi].x), "r"(av[mi].y), "r"(av[mi].z), "r"(av[mi].w),
                      "r"(bf[ni][0]), "r"(bf[ni][1]));
            }
    };

    int nk = kChunk / BK;

    // prologue: ktile 0 -> stage 0
    load_tiles(0, 0);
    __syncthreads();

    int s = 0;
    for (int kt = 0; kt < nk; kt++) {
        compute(s, 0);
        compute(s, 1);
        compute(s, 2);
        compute(s, 3);
        if (kt + 1 < nk) load_tiles(s ^ 1, (kt + 1) * BK);
        __syncthreads();
        s ^= 1;
    }

    // --- epilogue ---
#pragma unroll
    for (int mi = 0; mi < 4; mi++) {
        int r0 = bm + wm * 64 + mi * 16 + gp;
#pragma unroll
        for (int ni = 0; ni < 4; ni++) {
            int col = bn + wn * 32 + ni * 8 + 2 * tg;
            if (col >= N) continue;
            float b0 = bias ? bias[col] : 0.f;
            float b1 = bias ? bias[col + 1] : 0.f;
            if (r0 < M) {
                float v0 = c[mi][ni][0] + b0;
                float v1 = c[mi][ni][1] + b1;
                if (relu) { v0 = fmaxf(v0, 0.f); v1 = fmaxf(v1, 0.f); }
                *(float2*)(C + (size_t)r0 * N + col) = make_float2(v0, v1);
            }
            if (r0 + 8 < M) {
                float v2 = c[mi][ni][2] + b0;
                float v3 = c[mi][ni][3] + b1;
                if (relu) { v2 = fmaxf(v2, 0.f); v3 = fmaxf(v3, 0.f); }
                *(float2*)(C + (size_t)(r0 + 8) * N + col) = make_float2(v2, v3);
            }
        }
    }
}

// split-K reduce: out[i] = sum_s part[s*MN+i] (+ bias[i%N]); fixed order => deterministic
__global__ void splitk_reduce(const float* __restrict__ part, const float* __restrict__ bias,
                              float* __restrict__ out, int MN, int N, int S)
{
    int i = blockIdx.x * 256 + threadIdx.x;
    if (i >= MN) return;
    float acc = bias ? bias[i % N] : 0.f;
    for (int si = 0; si < S; si++) acc += part[(size_t)si * MN + i];
    out[i] = acc;
}

// ------------------------- IoU relation mask --------------------------------
__global__ void iou_mask_kernel(const float* __restrict__ bboxes,
                                const float* __restrict__ mask)
{
    int idx = blockIdx.x * blockDim.x + threadIdx.x;
    if (idx >= NB * NRQ * NRQ) return;
    int j = idx % NRQ;
    int i = (idx / NRQ) % NRQ;
    int n = idx / (NRQ * NRQ);
    const float* bi = bboxes + (size_t)(n * NRQ + i) * 4;
    const float* bj = bboxes + (size_t)(n * NRQ + j) * 4;
    float ax0 = bi[0], ay0 = bi[1], ax1 = bi[2], ay1 = bi[3];
    float bx0 = bj[0], by0 = bj[1], bx1 = bj[2], by1 = bj[3];
    float areaA = (ax1 - ax0) * (ay1 - ay0);
    float areaB = (bx1 - bx0) * (by1 - by0);
    float lx = fmaxf(ax0, bx0), ly = fmaxf(ay0, by0);
    float rx = fminf(ax1, bx1), ry = fminf(ay1, by1);
    float w = fmaxf(rx - lx, 0.f), h = fmaxf(ry - ly, 0.f);
    float inter = w * h;
    float uni = areaA + areaB - inter;
    float iou = inter / fmaxf(uni, 1e-9f);
    float mi = mask[n * NRQ + i], mj = mask[n * NRQ + j];
    bool masked = ((iou < 0.5f) && mi > 0.f && mj > 0.f) || (i == j && mi == 0.f);
    g_mflag[idx] = masked ? 1.f : 0.f;
}

// ------------------------- qk = pro + query ---------------------------------
__global__ void qkadd_kernel(const float* __restrict__ pro, const float* __restrict__ query)
{
    int idx = blockIdx.x * blockDim.x + threadIdx.x;
    if (idx >= ROWS * DIM) return;
    g_qk[idx] = pro[idx] + query[idx];
}

// ------------------------- attention scores ---------------------------------
__global__ void scores_kernel()
{
    int n = blockIdx.z, h = blockIdx.y, qt = blockIdx.x * 32;
    __shared__ float Qs[32][32];
    __shared__ float Ks[32][33];
    int tid = threadIdx.x;
    int r = tid / 32, c = tid % 32;
    for (int rr = r; rr < 32; rr += 8) {
        int q = qt + rr;
        Qs[rr][c] = (q < NRQ) ? g_qkp[(size_t)(n * NRQ + q) * 512 + h * 32 + c] : 0.f;
    }
    const float scale = 0.17677669529663687f;  // 1/sqrt(32)
    for (int kt = 0; kt < NRQ; kt += 32) {
        __syncthreads();
        for (int rr = r; rr < 32; rr += 8) {
            int k = kt + rr;
            Ks[rr][c] = (k < NRQ) ? g_qkp[(size_t)(n * NRQ + k) * 512 + 256 + h * 32 + c] : 0.f;
        }
        __syncthreads();
        int kk = tid % 32, qr0 = tid / 32;
        float acc[4] = {0.f, 0.f, 0.f, 0.f};
#pragma unroll
        for (int d = 0; d < 32; d++) {
            float kv = Ks[kk][d];
#pragma unroll
            for (int u = 0; u < 4; u++) acc[u] += Qs[qr0 + u * 8][d] * kv;
        }
#pragma unroll
        for (int u = 0; u < 4; u++) {
            int q = qt + qr0 + u * 8;
            int k = kt + kk;
            if (q < NRQ && k < NRQ) {
                float flag = g_mflag[(size_t)(n * NRQ + q) * NRQ + k];
                size_t off = ((size_t)(n * NHD + h) * NRQ + q) * NRQ + k;
                g_scores[off] = (flag > 0.f) ? -1e9f : acc[u] * scale;
            }
        }
    }
}

// ------------------------- row softmax (one warp per row) -------------------
__global__ void softmax_kernel()
{
    int row = blockIdx.x * 8 + threadIdx.x / 32;
    int lane = threadIdx.x % 32;
    if (row >= NB * NHD * NRQ) return;
    float* p = g_scores + (size_t)row * NRQ;
    float mx = -1e30f;
    for (int k = lane; k < NRQ; k += 32) mx = fmaxf(mx, p[k]);
    for (int o = 16; o; o >>= 1) mx = fmaxf(mx, __shfl_xor_sync(0xffffffffu, mx, o));
    float sum = 0.f;
    for (int k = lane; k < NRQ; k += 32) { float e = __expf(p[k] - mx); p[k] = e; sum += e; }
    for (int o = 16; o; o >>= 1) sum += __shfl_xor_sync(0xffffffffu, sum, o);
    float inv = 1.f / sum;
    for (int k = lane; k < NRQ; k += 32) p[k] *= inv;
}

// ------------------------- ctx = attn @ V -----------------------------------
__global__ void ctx_kernel()
{
    int idx = blockIdx.x * blockDim.x + threadIdx.x;
    if (idx >= ROWS * DIM) return;
    int col = idx & 255;
    int row = idx >> 8;             // n*NRQ + q
    int n = row / NRQ, q = row % NRQ;
    int h = col >> 5;
    const float* ap = g_scores + ((size_t)(n * NHD + h) * NRQ + q) * NRQ;
    float acc = 0.f;
    for (int k = 0; k < NRQ; k++)
        acc += ap[k] * g_vp[(size_t)(n * NRQ + k) * DIM + col];
    g_ctx[idx] = acc;
}

// ------------------------- LayerNorm rows of 256 ----------------------------
__global__ void ln_kernel(const float* __restrict__ x, const float* __restrict__ res,
                          const float* __restrict__ mask, float* __restrict__ out, int relu)
{
    int row = blockIdx.x;
    int c = threadIdx.x;
    size_t base = (size_t)row * DIM;
    float v = x[base + c];
    if (res) v += res[base + c];
    float s = v, q = v * v;
    for (int o = 16; o; o >>= 1) {
        s += __shfl_xor_sync(0xffffffffu, s, o);
        q += __shfl_xor_sync(0xffffffffu, q, o);
    }
    __shared__ float ss[8], sq[8];
    int w = c >> 5, lane = c & 31;
    if (lane == 0) { ss[w] = s; sq[w] = q; }
    __syncthreads();
    float tot = 0.f, totq = 0.f;
#pragma unroll
    for (int i = 0; i < 8; i++) { tot += ss[i]; totq += sq[i]; }
    float mean = tot * (1.f / DIM);
    float var = totq * (1.f / DIM) - mean * mean;
    float y = (v - mean) * rsqrtf(var + 1e-5f);
    if (relu) y = fmaxf(y, 0.f);
    if (mask) y *= mask[row];
    out[base + c] = y;
}

// ------------------------- DynamicConv per instance -------------------------
__global__ __launch_bounds__(256) void dynconv_kernel(const float* __restrict__ roi)
{
    extern __shared__ float sm[];
    float* fsm  = sm;                 // 12544
    float* psm  = sm + 12544;         // 16384
    float* f1sm = psm + 16384;        // 3136
    int n = blockIdx.x, tid = threadIdx.x;

    for (int i = tid; i < SS * DIM; i += 256) {
        int s = i >> 8, d = i & 255;
        fsm[i] = roi[((size_t)s * ROWS + n) * DIM + d];
    }
    const float* pr = g_params + (size_t)n * (2 * DIM * DDI);
    for (int i = tid; i < DIM * DDI; i += 256) psm[i] = pr[i];
    __syncthreads();

    int e = tid & 63, sb = tid >> 6;
    for (int s = sb; s < SS; s += 4) {
        float acc = 0.f;
        const float* fr = fsm + s * DIM;
#pragma unroll 8
        for (int d = 0; d < DIM; d++) acc += fr[d] * psm[d * DDI + e];
        f1sm[s * DDI + e] = acc;
    }
    __syncthreads();

    int wid = tid >> 5, lane = tid & 31;
    for (int s = wid; s < SS; s += 8) {
        float a = f1sm[s * DDI + lane], b = f1sm[s * DDI + 32 + lane];
        float sum = a + b, ssq = a * a + b * b;
        for (int o = 16; o; o >>= 1) {
            sum += __shfl_xor_sync(0xffffffffu, sum, o);
            ssq += __shfl_xor_sync(0xffffffffu, ssq, o);
        }
        float mean = sum * (1.f / 64.f);
        float var = ssq * (1.f / 64.f) - mean * mean;
        float inv = rsqrtf(var + 1e-5f);
        f1sm[s * DDI + lane]      = fmaxf((a - mean) * inv, 0.f);
        f1sm[s * DDI + 32 + lane] = fmaxf((b - mean) * inv, 0.f);
    }
    for (int i = tid; i < DIM * DDI; i += 256) psm[i] = pr[DIM * DDI + i];
    __syncthreads();

    for (int s = 0; s < SS; s++) {
        float acc = 0.f;
#pragma unroll 8
        for (int ee = 0; ee < DDI; ee++) acc += f1sm[s * DDI + ee] * psm[ee * DIM + tid];
        fsm[s * DIM + tid] = acc;
    }
    __syncthreads();

    for (int s = wid; s < SS; s += 8) {
        float vals[8];
        float sum = 0.f, ssq = 0.f;
#pragma unroll
        for (int u = 0; u < 8; u++) {
            float v = fsm[s * DIM + lane + u * 32];
            vals[u] = v; sum += v; ssq += v * v;
        }
        for (int o = 16; o; o >>= 1) {
            sum += __shfl_xor_sync(0xffffffffu, sum, o);
            ssq += __shfl_xor_sync(0xffffffffu, ssq, o);
        }
        float mean = sum * (1.f / DIM);
        float var = ssq * (1.f / DIM) - mean * mean;
        float inv = rsqrtf(var + 1e-5f);
#pragma unroll
        for (int u = 0; u < 8; u++) {
            float y = fmaxf((vals[u] - mean) * inv, 0.f);
            g_f2[(size_t)n * (SS * DIM) + s * DIM + lane + u * 32] = y;
        }
    }
}

// ------------------------- host launch --------------------------------------
template <typename T>
static float* sym(T& s) { void* p = nullptr; cudaGetSymbolAddress(&p, s); return (float*)p; }

#define GEMM_SMEM 65536

static void launch_gemm(const float* A, const float* B, const float* bias, float* C,
                        int M, int N, int K, int lda, int ldb, int relu, int splitS)
{
    static bool attr_set = false;
    if (!attr_set) {
        cudaFuncSetAttribute(gemm_tf32, cudaFuncAttributeMaxDynamicSharedMemorySize, GEMM_SMEM);
        attr_set = true;
    }
    dim3 g(cdiv(N, BN), cdiv(M, BM), splitS);
    gemm_tf32<<<g, 256, GEMM_SMEM>>>(A, B, bias, C, M, N, K / splitS, lda, ldb, relu);
}

extern "C" void kernel_launch(void* const* d_in, const int* in_sizes, int n_in,
                              void* d_out, int out_size)
{
    const float* bboxes   = (const float*)d_in[0];
    const float* pro      = (const float*)d_in[1];
    const float* roi      = (const float*)d_in[2];
    const float* query    = (const float*)d_in[3];
    const float* mask     = (const float*)d_in[4];
    const float* w_qkv    = (const float*)d_in[5];
    const float* b_qkv    = (const float*)d_in[6];
    const float* w_attn   = (const float*)d_in[7];
    const float* b_attn   = (const float*)d_in[8];
    const float* w_dyn    = (const float*)d_in[9];
    const float* b_dyn    = (const float*)d_in[10];
    const float* w_dyno   = (const float*)d_in[11];
    const float* b_dyno   = (const float*)d_in[12];
    const float* w_ff1    = (const float*)d_in[13];
    const float* b_ff1    = (const float*)d_in[14];
    const float* w_ff2    = (const float*)d_in[15];
    const float* b_ff2    = (const float*)d_in[16];
    const float* w_cls    = (const float*)d_in[17];
    const float* w_logits = (const float*)d_in[18];
    const float* b_logits = (const float*)d_in[19];
    float* out = (float*)d_out;

    float* p_qk    = sym(g_qk);
    float* p_qkp   = sym(g_qkp);
    float* p_vp    = sym(g_vp);
    float* p_ctx   = sym(g_ctx);
    float* p_tgt2  = sym(g_tgt2);
    float* p_pf1   = sym(g_pf1);
    float* p_params= sym(g_params);
    float* p_f2    = sym(g_f2);
    float* p_dynr  = sym(g_dynraw);
    float* p_pf2   = sym(g_pf2);
    float* p_pfB   = sym(g_pfB);
    float* p_ffh   = sym(g_ffh);
    float* p_t2    = sym(g_t2);
    float* p_fc    = sym(g_fc);
    float* p_g1    = sym(g_g1);
    float* p_clsf  = sym(g_clsf);

    // 1. IoU relation mask
    iou_mask_kernel<<<cdiv(NB * NRQ * NRQ, 256), 256>>>(bboxes, mask);
    // 2. qk = pro + query
    qkadd_kernel<<<cdiv(ROWS * DIM, 256), 256>>>(pro, query);
    // 3. q,k projection: [2400,512], split-K=2 (g_params free -> scratch)
    launch_gemm(p_qk, w_qkv, nullptr, p_params, ROWS, 512, DIM, DIM, DIM, 0, 2);
    splitk_reduce<<<cdiv(ROWS * 512, 256), 256>>>(p_params, b_qkv, p_qkp, ROWS * 512, 512, 2);
    // 4. v projection from pro_features, split-K=2 (use scratch past QK partials)
    {
        float* scr = p_params + 2 * ROWS * 512;
        launch_gemm(pro, w_qkv + 512 * DIM, nullptr, scr, ROWS, DIM, DIM, DIM, DIM, 0, 2);
        splitk_reduce<<<cdiv(ROWS * DIM, 256), 256>>>(scr, b_qkv + 512, p_vp, ROWS * DIM, DIM, 2);
    }
    // 5-7. attention
    {
        dim3 g(cdiv(NRQ, 32), NHD, NB);
        scores_kernel<<<g, 256>>>();
    }
    softmax_kernel<<<cdiv(NB * NHD * NRQ, 8), 256>>>();
    ctx_kernel<<<cdiv(ROWS * DIM, 256), 256>>>();
    // 8. out proj, split-K=2
    launch_gemm(p_ctx, w_attn, nullptr, p_params, ROWS, DIM, DIM, DIM, DIM, 0, 2);
    splitk_reduce<<<cdiv(ROWS * DIM, 256), 256>>>(p_params, b_attn, p_tgt2, ROWS * DIM, DIM, 2);
    // 9. norm1 + mask
    ln_kernel<<<ROWS, 256>>>(p_tgt2, pro, mask, p_pf1, 0);
    // 10. dyn params GEMM [2400, 32768] (full grid already)
    launch_gemm(p_pf1, w_dyn, b_dyn, p_params, ROWS, 2 * DIM * DDI, DIM, DIM, DIM, 0, 1);
    // 11. per-instance dynamic conv
    {
        int smem = (SS * DIM + DIM * DDI + SS * DDI) * 4;  // 128256 B
        cudaFuncSetAttribute(dynconv_kernel, cudaFuncAttributeMaxDynamicSharedMemorySize, smem);
        dynconv_kernel<<<ROWS, 256, smem>>>(roi);
    }
    // 12. out_layer GEMM: [2400,256], K=12544, split-K=8 (g_params free -> scratch)
    launch_gemm(p_f2, w_dyno, nullptr, p_params, ROWS, DIM, SS * DIM, SS * DIM, SS * DIM, 0, 8);
    splitk_reduce<<<cdiv(ROWS * DIM, 256), 256>>>(p_params, b_dyno, p_dynr, ROWS * DIM, DIM, 8);
    // 13. pf2 = relu(ln(dynraw))
    ln_kernel<<<ROWS, 256>>>(p_dynr, nullptr, nullptr, p_pf2, 1);
    // 14. norm2: pfB = ln(pf1 + pf2)
    ln_kernel<<<ROWS, 256>>>(p_pf2, p_pf1, nullptr, p_pfB, 0);
    // 15. FFN 1 (relu)
    launch_gemm(p_pfB, w_ff1, b_ff1, p_ffh, ROWS, FFD, DIM, DIM, DIM, 1, 1);
    // 16. FFN 2, split-K=4
    launch_gemm(p_ffh, w_ff2, nullptr, p_params, ROWS, DIM, FFD, FFD, FFD, 0, 4);
    splitk_reduce<<<cdiv(ROWS * DIM, 256), 256>>>(p_params, b_ff2, p_t2, ROWS * DIM, DIM, 4);
    // 17. norm3 + mask -> fc
    ln_kernel<<<ROWS, 256>>>(p_t2, p_pfB, mask, p_fc, 0);
    // 18. cls tower linear (no bias), split-K=2
    launch_gemm(p_fc, w_cls, nullptr, p_params, ROWS, DIM, DIM, DIM, DIM, 0, 2);
    splitk_reduce<<<cdiv(ROWS * DIM, 256), 256>>>(p_params, nullptr, p_g1, ROWS * DIM, DIM, 2);
    // 19. cls_f = relu(ln(g1))
    ln_kernel<<<ROWS, 256>>>(p_g1, nullptr, nullptr, p_clsf, 1);
    // 20. logits -> d_out [2400, 80], split-K=2
    launch_gemm(p_clsf, w_logits, nullptr, p_params, ROWS, NCLS, DIM, DIM, DIM, 0, 2);
    splitk_reduce<<<cdiv(ROWS * NCLS, 256), 256>>>(p_params, b_logits, out, ROWS * NCLS, NCLS, 2);
}

// round 15
// speedup vs baseline: 3.7700x; 1.2614x over previous
#include <cuda_runtime.h>
#include <cstdint>
#include <cstddef>

#define NB   8
#define NRQ  300
#define DIM  256
#define NHD  8
#define HDM  32
#define SS   49
#define DDI  64
#define FFD  2048
#define NCLS 80
#define ROWS 2400   // NB*NRQ

// ------------------------- scratch (device globals) -------------------------
__device__ float g_qk   [ROWS * DIM];
__device__ float g_qkp  [ROWS * 512];                 // q proj | k proj
__device__ float g_vp   [ROWS * DIM];
__device__ float g_mflag[NB * NRQ * NRQ];             // 1 = masked
__device__ float g_scores[(size_t)NB * NHD * NRQ * NRQ];
__device__ float g_ctx  [ROWS * DIM];
__device__ float g_tgt2 [ROWS * DIM];
__device__ float g_pf1  [ROWS * DIM];
__device__ float g_params[(size_t)ROWS * 2 * DIM * DDI];   // 314 MB (also split-K scratch)
__device__ float g_f2   [(size_t)ROWS * SS * DIM];         // 120 MB
__device__ float g_dynraw[ROWS * DIM];
__device__ float g_pf2  [ROWS * DIM];
__device__ float g_pfB  [ROWS * DIM];
__device__ float g_ffh  [(size_t)ROWS * FFD];
__device__ float g_t2   [ROWS * DIM];
__device__ float g_fc   [ROWS * DIM];
__device__ float g_g1   [ROWS * DIM];
__device__ float g_clsf [ROWS * DIM];

static inline int cdiv(int a, int b) { return (a + b - 1) / b; }

// ------------------------- TF32 tensor-core GEMM ----------------------------
// C = A * B^T (+bias) (optional relu). A[M,K] rm (lda), B[N,K] rm (ldb).
// kChunk % 32 == 0. blockIdx.z = split-K slice (A,B advance z*kChunk; C by z*M*N).
// CTA tile 128x128x32, 8 warps (2m x 4n), warp tile 64x32, m16n8k8 tf32.
// Smem in FRAGMENT ORDER (tf32-converted), LDS.128/STS.128 conflict-free.
#define BM 128
#define BN 128
#define BK 32

__device__ __forceinline__ uint32_t f2tf32(float f) {
    uint32_t u;
    asm("cvt.rna.tf32.f32 %0, %1;" : "=r"(u) : "f"(f));
    return u;
}

__global__ __launch_bounds__(256, 2) void gemm_tf32(
    const float* __restrict__ A, const float* __restrict__ B,
    const float* __restrict__ bias, float* __restrict__ C,
    int M, int N, int kChunk, int lda, int ldb, int relu)
{
    extern __shared__ uint32_t dynsm[];           // [2][8192]: A at +0, B at +4096
    int tid = threadIdx.x;
    int lane = tid & 31;
    int wrp = tid >> 5;
    int gp = lane >> 2, tg = lane & 3;
    int bm = blockIdx.y * BM, bn = blockIdx.x * BN;

    // split-K slice offsets
    A += (size_t)blockIdx.z * kChunk;
    B += (size_t)blockIdx.z * kChunk;
    C += (size_t)blockIdx.z * M * N;

    int wm = wrp & 1, wn = wrp >> 1;

    float c[4][4][4];
#pragma unroll
    for (int mi = 0; mi < 4; mi++)
#pragma unroll
        for (int ni = 0; ni < 4; ni++)
#pragma unroll
            for (int r = 0; r < 4; r++) c[mi][ni][r] = 0.f;

    // Load one ktile (A+B) into stage s at k-offset koff.
    auto load_tiles = [&](int s, int koff) {
#pragma unroll
        for (int i = 0; i < 4; i++) {
            int cc = wrp + 8 * i;
            int ks = cc >> 3;
            int kk = ks * 8 + tg + koff;
            uint32_t soff = (uint32_t)(cc << 7) + (uint32_t)(lane << 2);
            {
                int wmc = (cc >> 2) & 1, mi = cc & 3;
                int row = bm + wmc * 64 + mi * 16 + gp;
                const float* p = A + (size_t)row * lda + kk;
                bool ok0 = row < M, ok1 = (row + 8) < M;
                float x0 = ok0 ? p[0] : 0.f;
                float x1 = ok1 ? p[(size_t)8 * lda] : 0.f;
                float x2 = ok0 ? p[4] : 0.f;
                float x3 = ok1 ? p[(size_t)8 * lda + 4] : 0.f;
                uint4 u;
                u.x = f2tf32(x0); u.y = f2tf32(x1); u.z = f2tf32(x2); u.w = f2tf32(x3);
                *(uint4*)&dynsm[s * 8192 + soff] = u;
            }
            {
                int wnc = (cc & 7) >> 1, h = cc & 1;
                int col = bn + wnc * 32 + h * 16 + gp;
                const float* p = B + (size_t)col * ldb + kk;
                bool ok0 = col < N, ok1 = (col + 8) < N;
                float x0 = ok0 ? p[0] : 0.f;
                float x1 = ok0 ? p[4] : 0.f;
                float x2 = ok1 ? p[(size_t)8 * ldb] : 0.f;
                float x3 = ok1 ? p[(size_t)8 * ldb + 4] : 0.f;
                uint4 u;
                u.x = f2tf32(x0); u.y = f2tf32(x1); u.z = f2tf32(x2); u.w = f2tf32(x3);
                *(uint4*)&dynsm[s * 8192 + 4096 + soff] = u;
            }
        }
    };

    auto compute = [&](int s, int ks) {
        const uint32_t* smA = dynsm + s * 8192;
        const uint32_t* smB = smA + 4096;
        uint4 av[4];
#pragma unroll
        for (int mi = 0; mi < 4; mi++)
            av[mi] = *(const uint4*)&smA[((ks * 8 + wm * 4 + mi) << 7) + (lane << 2)];
        uint4 bv0 = *(const uint4*)&smB[((ks * 8 + wn * 2 + 0) << 7) + (lane << 2)];
        uint4 bv1 = *(const uint4*)&smB[((ks * 8 + wn * 2 + 1) << 7) + (lane << 2)];
        uint32_t bf[4][2] = {{bv0.x, bv0.y}, {bv0.z, bv0.w}, {bv1.x, bv1.y}, {bv1.z, bv1.w}};
#pragma unroll
        for (int mi = 0; mi < 4; mi++)
#pragma unroll
            for (int ni = 0; ni < 4; ni++) {
                asm volatile(
                    "mma.sync.aligned.m16n8k8.row.col.f32.tf32.tf32.f32 "
                    "{%0,%1,%2,%3}, {%4,%5,%6,%7}, {%8,%9}, {%0,%1,%2,%3};"
                    : "+f"(c[mi][ni][0]), "+f"(c[mi][ni][1]),
                      "+f"(c[mi][ni][2]), "+f"(c[mi][ni][3])
                    : "r"(av[mi].x), "r"(av[mi].y), "r"(av[mi].z), "r"(av[mi].w),
                      "r"(bf[ni][0]), "r"(bf[ni][1]));
            }
    };

    int nk = kChunk / BK;

    load_tiles(0, 0);
    __syncthreads();

    int s = 0;
    for (int kt = 0; kt < nk; kt++) {
        compute(s, 0);
        compute(s, 1);
        compute(s, 2);
        compute(s, 3);
        if (kt + 1 < nk) load_tiles(s ^ 1, (kt + 1) * BK);
        __syncthreads();
        s ^= 1;
    }

    // --- epilogue ---
#pragma unroll
    for (int mi = 0; mi < 4; mi++) {
        int r0 = bm + wm * 64 + mi * 16 + gp;
#pragma unroll
        for (int ni = 0; ni < 4; ni++) {
            int col = bn + wn * 32 + ni * 8 + 2 * tg;
            if (col >= N) continue;
            float b0 = bias ? bias[col] : 0.f;
            float b1 = bias ? bias[col + 1] : 0.f;
            if (r0 < M) {
                float v0 = c[mi][ni][0] + b0;
                float v1 = c[mi][ni][1] + b1;
                if (relu) { v0 = fmaxf(v0, 0.f); v1 = fmaxf(v1, 0.f); }
                *(float2*)(C + (size_t)r0 * N + col) = make_float2(v0, v1);
            }
            if (r0 + 8 < M) {
                float v2 = c[mi][ni][2] + b0;
                float v3 = c[mi][ni][3] + b1;
                if (relu) { v2 = fmaxf(v2, 0.f); v3 = fmaxf(v3, 0.f); }
                *(float2*)(C + (size_t)(r0 + 8) * N + col) = make_float2(v2, v3);
            }
        }
    }
}

// split-K reduce: out[i] = sum_s part[s*MN+i] (+ bias[i%N]); fixed order => deterministic
__global__ void splitk_reduce(const float* __restrict__ part, const float* __restrict__ bias,
                              float* __restrict__ out, int MN, int N, int S)
{
    int i = blockIdx.x * 256 + threadIdx.x;
    if (i >= MN) return;
    float acc = bias ? bias[i % N] : 0.f;
    for (int si = 0; si < S; si++) acc += part[(size_t)si * MN + i];
    out[i] = acc;
}

// ------------------------- IoU relation mask --------------------------------
__global__ void iou_mask_kernel(const float* __restrict__ bboxes,
                                const float* __restrict__ mask)
{
    int idx = blockIdx.x * blockDim.x + threadIdx.x;
    if (idx >= NB * NRQ * NRQ) return;
    int j = idx % NRQ;
    int i = (idx / NRQ) % NRQ;
    int n = idx / (NRQ * NRQ);
    const float* bi = bboxes + (size_t)(n * NRQ + i) * 4;
    const float* bj = bboxes + (size_t)(n * NRQ + j) * 4;
    float ax0 = bi[0], ay0 = bi[1], ax1 = bi[2], ay1 = bi[3];
    float bx0 = bj[0], by0 = bj[1], bx1 = bj[2], by1 = bj[3];
    float areaA = (ax1 - ax0) * (ay1 - ay0);
    float areaB = (bx1 - bx0) * (by1 - by0);
    float lx = fmaxf(ax0, bx0), ly = fmaxf(ay0, by0);
    float rx = fminf(ax1, bx1), ry = fminf(ay1, by1);
    float w = fmaxf(rx - lx, 0.f), h = fmaxf(ry - ly, 0.f);
    float inter = w * h;
    float uni = areaA + areaB - inter;
    float iou = inter / fmaxf(uni, 1e-9f);
    float mi = mask[n * NRQ + i], mj = mask[n * NRQ + j];
    bool masked = ((iou < 0.5f) && mi > 0.f && mj > 0.f) || (i == j && mi == 0.f);
    g_mflag[idx] = masked ? 1.f : 0.f;
}

// ------------------------- qk = pro + query ---------------------------------
__global__ void qkadd_kernel(const float* __restrict__ pro, const float* __restrict__ query)
{
    int idx = blockIdx.x * blockDim.x + threadIdx.x;
    if (idx >= ROWS * DIM) return;
    g_qk[idx] = pro[idx] + query[idx];
}

// ------------------------- attention scores ---------------------------------
__global__ void scores_kernel()
{
    int n = blockIdx.z, h = blockIdx.y, qt = blockIdx.x * 32;
    __shared__ float Qs[32][32];
    __shared__ float Ks[32][33];
    int tid = threadIdx.x;
    int r = tid / 32, c = tid % 32;
    for (int rr = r; rr < 32; rr += 8) {
        int q = qt + rr;
        Qs[rr][c] = (q < NRQ) ? g_qkp[(size_t)(n * NRQ + q) * 512 + h * 32 + c] : 0.f;
    }
    const float scale = 0.17677669529663687f;  // 1/sqrt(32)
    for (int kt = 0; kt < NRQ; kt += 32) {
        __syncthreads();
        for (int rr = r; rr < 32; rr += 8) {
            int k = kt + rr;
            Ks[rr][c] = (k < NRQ) ? g_qkp[(size_t)(n * NRQ + k) * 512 + 256 + h * 32 + c] : 0.f;
        }
        __syncthreads();
        int kk = tid % 32, qr0 = tid / 32;
        float acc[4] = {0.f, 0.f, 0.f, 0.f};
#pragma unroll
        for (int d = 0; d < 32; d++) {
            float kv = Ks[kk][d];
#pragma unroll
            for (int u = 0; u < 4; u++) acc[u] += Qs[qr0 + u * 8][d] * kv;
        }
#pragma unroll
        for (int u = 0; u < 4; u++) {
            int q = qt + qr0 + u * 8;
            int k = kt + kk;
            if (q < NRQ && k < NRQ) {
                float flag = g_mflag[(size_t)(n * NRQ + q) * NRQ + k];
                size_t off = ((size_t)(n * NHD + h) * NRQ + q) * NRQ + k;
                g_scores[off] = (flag > 0.f) ? -1e9f : acc[u] * scale;
            }
        }
    }
}

// ------------------------- row softmax (one warp per row) -------------------
__global__ void softmax_kernel()
{
    int row = blockIdx.x * 8 + threadIdx.x / 32;
    int lane = threadIdx.x % 32;
    if (row >= NB * NHD * NRQ) return;
    float* p = g_scores + (size_t)row * NRQ;
    float mx = -1e30f;
    for (int k = lane; k < NRQ; k += 32) mx = fmaxf(mx, p[k]);
    for (int o = 16; o; o >>= 1) mx = fmaxf(mx, __shfl_xor_sync(0xffffffffu, mx, o));
    float sum = 0.f;
    for (int k = lane; k < NRQ; k += 32) { float e = __expf(p[k] - mx); p[k] = e; sum += e; }
    for (int o = 16; o; o >>= 1) sum += __shfl_xor_sync(0xffffffffu, sum, o);
    float inv = 1.f / sum;
    for (int k = lane; k < NRQ; k += 32) p[k] *= inv;
}

// ------------------------- ctx = attn @ V -----------------------------------
__global__ void ctx_kernel()
{
    int idx = blockIdx.x * blockDim.x + threadIdx.x;
    if (idx >= ROWS * DIM) return;
    int col = idx & 255;
    int row = idx >> 8;             // n*NRQ + q
    int n = row / NRQ, q = row % NRQ;
    int h = col >> 5;
    const float* ap = g_scores + ((size_t)(n * NHD + h) * NRQ + q) * NRQ;
    float acc = 0.f;
    for (int k = 0; k < NRQ; k++)
        acc += ap[k] * g_vp[(size_t)(n * NRQ + k) * DIM + col];
    g_ctx[idx] = acc;
}

// ------------------------- LayerNorm rows of 256 ----------------------------
__global__ void ln_kernel(const float* __restrict__ x, const float* __restrict__ res,
                          const float* __restrict__ mask, float* __restrict__ out, int relu)
{
    int row = blockIdx.x;
    int c = threadIdx.x;
    size_t base = (size_t)row * DIM;
    float v = x[base + c];
    if (res) v += res[base + c];
    float s = v, q = v * v;
    for (int o = 16; o; o >>= 1) {
        s += __shfl_xor_sync(0xffffffffu, s, o);
        q += __shfl_xor_sync(0xffffffffu, q, o);
    }
    __shared__ float ss[8], sq[8];
    int w = c >> 5, lane = c & 31;
    if (lane == 0) { ss[w] = s; sq[w] = q; }
    __syncthreads();
    float tot = 0.f, totq = 0.f;
#pragma unroll
    for (int i = 0; i < 8; i++) { tot += ss[i]; totq += sq[i]; }
    float mean = tot * (1.f / DIM);
    float var = totq * (1.f / DIM) - mean * mean;
    float y = (v - mean) * rsqrtf(var + 1e-5f);
    if (relu) y = fmaxf(y, 0.f);
    if (mask) y *= mask[row];
    out[base + c] = y;
}

// ------------------------- DynamicConv per instance -------------------------
// Register-blocked 4x4 tiles + float4 LDS: LDS/FMA drops from 2.0 to ~0.12,
// moving both product stages from LDS-crossbar-bound to FMA-bound.
// Summation order over K is unchanged -> bit-identical to previous version.
__global__ __launch_bounds__(256) void dynconv_kernel(const float* __restrict__ roi)
{
    extern __shared__ float sm[];
    float* fsm  = sm;                 // 12544 (feats, later f2 raw)
    float* psm  = sm + 12544;         // 16384 (p1, later p2)
    float* f1sm = psm + 16384;        // 3136
    int n = blockIdx.x, tid = threadIdx.x;

    for (int i = tid; i < SS * DIM; i += 256) {
        int s = i >> 8, d = i & 255;
        fsm[i] = roi[((size_t)s * ROWS + n) * DIM + d];
    }
    const float* pr = g_params + (size_t)n * (2 * DIM * DDI);
    for (int i = tid; i < DIM * DDI; i += 256) psm[i] = pr[i];
    __syncthreads();

    // ---- f1[s][e] = sum_d feats[s][d] * p1[d][e], 4s x 4e per thread ----
    {
        int eg = tid & 15, sg = tid >> 4;       // eg 0..15, sg 0..15
        int e0 = eg * 4, s0 = sg * 4;
        if (s0 < SS) {
            float acc[4][4];
#pragma unroll
            for (int i = 0; i < 4; i++)
#pragma unroll
                for (int j = 0; j < 4; j++) acc[i][j] = 0.f;
            int srow[4];
#pragma unroll
            for (int i = 0; i < 4; i++)
                srow[i] = ((s0 + i < SS) ? (s0 + i) : (SS - 1)) * DIM;
            for (int d = 0; d < DIM; d += 4) {
                float fa[4][4];
#pragma unroll
                for (int i = 0; i < 4; i++) {
                    float4 f4 = *(const float4*)&fsm[srow[i] + d];
                    fa[i][0] = f4.x; fa[i][1] = f4.y; fa[i][2] = f4.z; fa[i][3] = f4.w;
                }
#pragma unroll
                for (int dd = 0; dd < 4; dd++) {
                    float4 p = *(const float4*)&psm[(d + dd) * DDI + e0];
                    float pa[4] = {p.x, p.y, p.z, p.w};
#pragma unroll
                    for (int i = 0; i < 4; i++)
#pragma unroll
                        for (int j = 0; j < 4; j++)
                            acc[i][j] = fmaf(fa[i][dd], pa[j], acc[i][j]);
                }
            }
#pragma unroll
            for (int i = 0; i < 4; i++) {
                if (s0 + i < SS) {
#pragma unroll
                    for (int j = 0; j < 4; j++)
                        f1sm[(s0 + i) * DDI + e0 + j] = acc[i][j];
                }
            }
        }
    }
    __syncthreads();

    // ---- ln over 64 + relu (one warp per row, in-place) ----
    int wid = tid >> 5, lane = tid & 31;
    for (int s = wid; s < SS; s += 8) {
        float a = f1sm[s * DDI + lane], b = f1sm[s * DDI + 32 + lane];
        float sum = a + b, ssq = a * a + b * b;
        for (int o = 16; o; o >>= 1) {
            sum += __shfl_xor_sync(0xffffffffu, sum, o);
            ssq += __shfl_xor_sync(0xffffffffu, ssq, o);
        }
        float mean = sum * (1.f / 64.f);
        float var = ssq * (1.f / 64.f) - mean * mean;
        float inv = rsqrtf(var + 1e-5f);
        f1sm[s * DDI + lane]      = fmaxf((a - mean) * inv, 0.f);
        f1sm[s * DDI + 32 + lane] = fmaxf((b - mean) * inv, 0.f);
    }
    // reload psm with p2 (f1 stage done with p1; LN touches only f1sm)
    for (int i = tid; i < DIM * DDI; i += 256) psm[i] = pr[DIM * DDI + i];
    __syncthreads();

    // ---- f2[s][d] = sum_e f1[s][e] * p2[e][d], 4s x 4d per thread ----
    {
        int dg = tid & 63, so = tid >> 6;       // dg 0..63, so 0..3
        int d0 = dg * 4;
        for (int sb = so * 4; sb < SS; sb += 16) {
            float acc[4][4];
#pragma unroll
            for (int i = 0; i < 4; i++)
#pragma unroll
                for (int j = 0; j < 4; j++) acc[i][j] = 0.f;
            int srow[4];
#pragma unroll
            for (int i = 0; i < 4; i++)
                srow[i] = ((sb + i < SS) ? (sb + i) : (SS - 1)) * DDI;
            for (int e = 0; e < DDI; e += 4) {
                float fa[4][4];
#pragma unroll
                for (int i = 0; i < 4; i++) {
                    float4 f4 = *(const float4*)&f1sm[srow[i] + e];
                    fa[i][0] = f4.x; fa[i][1] = f4.y; fa[i][2] = f4.z; fa[i][3] = f4.w;
                }
#pragma unroll
                for (int ee = 0; ee < 4; ee++) {
                    float4 p = *(const float4*)&psm[(e + ee) * DIM + d0];
                    float pa[4] = {p.x, p.y, p.z, p.w};
#pragma unroll
                    for (int i = 0; i < 4; i++)
#pragma unroll
                        for (int j = 0; j < 4; j++)
                            acc[i][j] = fmaf(fa[i][ee], pa[j], acc[i][j]);
                }
            }
#pragma unroll
            for (int i = 0; i < 4; i++) {
                if (sb + i < SS) {
#pragma unroll
                    for (int j = 0; j < 4; j++)
                        fsm[(sb + i) * DIM + d0 + j] = acc[i][j];
                }
            }
        }
    }
    __syncthreads();

    // ---- ln over 256 + relu, write to g_f2 ----
    for (int s = wid; s < SS; s += 8) {
        float vals[8];
        float sum = 0.f, ssq = 0.f;
#pragma unroll
        for (int u = 0; u < 8; u++) {
            float v = fsm[s * DIM + lane + u * 32];
            vals[u] = v; sum += v; ssq += v * v;
        }
        for (int o = 16; o; o >>= 1) {
            sum += __shfl_xor_sync(0xffffffffu, sum, o);
            ssq += __shfl_xor_sync(0xffffffffu, ssq, o);
        }
        float mean = sum * (1.f / DIM);
        float var = ssq * (1.f / DIM) - mean * mean;
        float inv = rsqrtf(var + 1e-5f);
#pragma unroll
        for (int u = 0; u < 8; u++) {
            float y = fmaxf((vals[u] - mean) * inv, 0.f);
            g_f2[(size_t)n * (SS * DIM) + s * DIM + lane + u * 32] = y;
        }
    }
}

// ------------------------- host launch --------------------------------------
template <typename T>
static float* sym(T& s) { void* p = nullptr; cudaGetSymbolAddress(&p, s); return (float*)p; }

#define GEMM_SMEM 65536

static void launch_gemm(const float* A, const float* B, const float* bias, float* C,
                        int M, int N, int K, int lda, int ldb, int relu, int splitS)
{
    static bool attr_set = false;
    if (!attr_set) {
        cudaFuncSetAttribute(gemm_tf32, cudaFuncAttributeMaxDynamicSharedMemorySize, GEMM_SMEM);
        attr_set = true;
    }
    dim3 g(cdiv(N, BN), cdiv(M, BM), splitS);
    gemm_tf32<<<g, 256, GEMM_SMEM>>>(A, B, bias, C, M, N, K / splitS, lda, ldb, relu);
}

extern "C" void kernel_launch(void* const* d_in, const int* in_sizes, int n_in,
                              void* d_out, int out_size)
{
    const float* bboxes   = (const float*)d_in[0];
    const float* pro      = (const float*)d_in[1];
    const float* roi      = (const float*)d_in[2];
    const float* query    = (const float*)d_in[3];
    const float* mask     = (const float*)d_in[4];
    const float* w_qkv    = (const float*)d_in[5];
    const float* b_qkv    = (const float*)d_in[6];
    const float* w_attn   = (const float*)d_in[7];
    const float* b_attn   = (const float*)d_in[8];
    const float* w_dyn    = (const float*)d_in[9];
    const float* b_dyn    = (const float*)d_in[10];
    const float* w_dyno   = (const float*)d_in[11];
    const float* b_dyno   = (const float*)d_in[12];
    const float* w_ff1    = (const float*)d_in[13];
    const float* b_ff1    = (const float*)d_in[14];
    const float* w_ff2    = (const float*)d_in[15];
    const float* b_ff2    = (const float*)d_in[16];
    const float* w_cls    = (const float*)d_in[17];
    const float* w_logits = (const float*)d_in[18];
    const float* b_logits = (const float*)d_in[19];
    float* out = (float*)d_out;

    float* p_qk    = sym(g_qk);
    float* p_qkp   = sym(g_qkp);
    float* p_vp    = sym(g_vp);
    float* p_ctx   = sym(g_ctx);
    float* p_tgt2  = sym(g_tgt2);
    float* p_pf1   = sym(g_pf1);
    float* p_params= sym(g_params);
    float* p_f2    = sym(g_f2);
    float* p_dynr  = sym(g_dynraw);
    float* p_pf2   = sym(g_pf2);
    float* p_pfB   = sym(g_pfB);
    float* p_ffh   = sym(g_ffh);
    float* p_t2    = sym(g_t2);
    float* p_fc    = sym(g_fc);
    float* p_g1    = sym(g_g1);
    float* p_clsf  = sym(g_clsf);

    // 1. IoU relation mask
    iou_mask_kernel<<<cdiv(NB * NRQ * NRQ, 256), 256>>>(bboxes, mask);
    // 2. qk = pro + query
    qkadd_kernel<<<cdiv(ROWS * DIM, 256), 256>>>(pro, query);
    // 3. q,k projection: [2400,512], split-K=2 (g_params free -> scratch)
    launch_gemm(p_qk, w_qkv, nullptr, p_params, ROWS, 512, DIM, DIM, DIM, 0, 2);
    splitk_reduce<<<cdiv(ROWS * 512, 256), 256>>>(p_params, b_qkv, p_qkp, ROWS * 512, 512, 2);
    // 4. v projection from pro_features, split-K=2 (use scratch past QK partials)
    {
        float* scr = p_params + 2 * ROWS * 512;
        launch_gemm(pro, w_qkv + 512 * DIM, nullptr, scr, ROWS, DIM, DIM, DIM, DIM, 0, 2);
        splitk_reduce<<<cdiv(ROWS * DIM, 256), 256>>>(scr, b_qkv + 512, p_vp, ROWS * DIM, DIM, 2);
    }
    // 5-7. attention
    {
        dim3 g(cdiv(NRQ, 32), NHD, NB);
        scores_kernel<<<g, 256>>>();
    }
    softmax_kernel<<<cdiv(NB * NHD * NRQ, 8), 256>>>();
    ctx_kernel<<<cdiv(ROWS * DIM, 256), 256>>>();
    // 8. out proj, split-K=2
    launch_gemm(p_ctx, w_attn, nullptr, p_params, ROWS, DIM, DIM, DIM, DIM, 0, 2);
    splitk_reduce<<<cdiv(ROWS * DIM, 256), 256>>>(p_params, b_attn, p_tgt2, ROWS * DIM, DIM, 2);
    // 9. norm1 + mask
    ln_kernel<<<ROWS, 256>>>(p_tgt2, pro, mask, p_pf1, 0);
    // 10. dyn params GEMM [2400, 32768] (full grid already)
    launch_gemm(p_pf1, w_dyn, b_dyn, p_params, ROWS, 2 * DIM * DDI, DIM, DIM, DIM, 0, 1);
    // 11. per-instance dynamic conv (register-blocked)
    {
        int smem = (SS * DIM + DIM * DDI + SS * DDI) * 4;  // 128256 B
        cudaFuncSetAttribute(dynconv_kernel, cudaFuncAttributeMaxDynamicSharedMemorySize, smem);
        dynconv_kernel<<<ROWS, 256, smem>>>(roi);
    }
    // 12. out_layer GEMM: [2400,256], K=12544, split-K=8 (g_params free -> scratch)
    launch_gemm(p_f2, w_dyno, nullptr, p_params, ROWS, DIM, SS * DIM, SS * DIM, SS * DIM, 0, 8);
    splitk_reduce<<<cdiv(ROWS * DIM, 256), 256>>>(p_params, b_dyno, p_dynr, ROWS * DIM, DIM, 8);
    // 13. pf2 = relu(ln(dynraw))
    ln_kernel<<<ROWS, 256>>>(p_dynr, nullptr, nullptr, p_pf2, 1);
    // 14. norm2: pfB = ln(pf1 + pf2)
    ln_kernel<<<ROWS, 256>>>(p_pf2, p_pf1, nullptr, p_pfB, 0);
    // 15. FFN 1 (relu)
    launch_gemm(p_pfB, w_ff1, b_ff1, p_ffh, ROWS, FFD, DIM, DIM, DIM, 1, 1);
    // 16. FFN 2, split-K=4
    launch_gemm(p_ffh, w_ff2, nullptr, p_params, ROWS, DIM, FFD, FFD, FFD, 0, 4);
    splitk_reduce<<<cdiv(ROWS * DIM, 256), 256>>>(p_params, b_ff2, p_t2, ROWS * DIM, DIM, 4);
    // 17. norm3 + mask -> fc
    ln_kernel<<<ROWS, 256>>>(p_t2, p_pfB, mask, p_fc, 0);
    // 18. cls tower linear (no bias), split-K=2
    launch_gemm(p_fc, w_cls, nullptr, p_params, ROWS, DIM, DIM, DIM, DIM, 0, 2);
    splitk_reduce<<<cdiv(ROWS * DIM, 256), 256>>>(p_params, nullptr, p_g1, ROWS * DIM, DIM, 2);
    // 19. cls_f = relu(ln(g1))
    ln_kernel<<<ROWS, 256>>>(p_g1, nullptr, nullptr, p_clsf, 1);
    // 20. logits -> d_out [2400, 80], split-K=2
    launch_gemm(p_clsf, w_logits, nullptr, p_params, ROWS, NCLS, DIM, DIM, DIM, 0, 2);
    splitk_reduce<<<cdiv(ROWS * NCLS, 256), 256>>>(p_params, b_logits, out, ROWS * NCLS, NCLS, 2);
}

// round 17
// speedup vs baseline: 4.6211x; 1.2258x over previous
#include <cuda_runtime.h>
#include <cstdint>
#include <cstddef>

#define NB   8
#define NRQ  300
#define DIM  256
#define NHD  8
#define HDM  32
#define SS   49
#define DDI  64
#define FFD  2048
#define NCLS 80
#define ROWS 2400   // NB*NRQ

// ------------------------- scratch (device globals) -------------------------
__device__ float g_qk   [ROWS * DIM];
__device__ float g_qkp  [ROWS * 512];                 // q proj | k proj
__device__ float g_vp   [ROWS * DIM];
__device__ float g_mflag[NB * NRQ * NRQ];             // 1 = masked
__device__ float g_scores[(size_t)NB * NHD * NRQ * NRQ];
__device__ float g_ctx  [ROWS * DIM];
__device__ float g_tgt2 [ROWS * DIM];
__device__ float g_pf1  [ROWS * DIM];
__device__ float g_params[(size_t)ROWS * 2 * DIM * DDI];   // 314 MB (also split-K scratch)
__device__ float g_f2   [(size_t)ROWS * SS * DIM];         // 120 MB
__device__ float g_dynraw[ROWS * DIM];
__device__ float g_pf2  [ROWS * DIM];
__device__ float g_pfB  [ROWS * DIM];
__device__ float g_ffh  [(size_t)ROWS * FFD];
__device__ float g_t2   [ROWS * DIM];
__device__ float g_fc   [ROWS * DIM];
__device__ float g_g1   [ROWS * DIM];
__device__ float g_clsf [ROWS * DIM];

static inline int cdiv(int a, int b) { return (a + b - 1) / b; }

// ------------------------- TF32 tensor-core GEMM ----------------------------
// C = A * B^T (+bias) (optional relu). A[M,K] rm (lda), B[N,K] rm (ldb).
// kChunk % 32 == 0. blockIdx.z = split-K slice (A,B advance z*kChunk; C by z*M*N).
// CTA tile 128x128x32, 8 warps (2m x 4n), warp tile 64x32, m16n8k8 tf32.
// Smem in FRAGMENT ORDER (tf32-converted), LDS.128/STS.128 conflict-free.
#define BM 128
#define BN 128
#define BK 32

__device__ __forceinline__ uint32_t f2tf32(float f) {
    uint32_t u;
    asm("cvt.rna.tf32.f32 %0, %1;" : "=r"(u) : "f"(f));
    return u;
}

__global__ __launch_bounds__(256, 2) void gemm_tf32(
    const float* __restrict__ A, const float* __restrict__ B,
    const float* __restrict__ bias, float* __restrict__ C,
    int M, int N, int kChunk, int lda, int ldb, int relu)
{
    extern __shared__ uint32_t dynsm[];           // [2][8192]: A at +0, B at +4096
    int tid = threadIdx.x;
    int lane = tid & 31;
    int wrp = tid >> 5;
    int gp = lane >> 2, tg = lane & 3;
    int bm = blockIdx.y * BM, bn = blockIdx.x * BN;

    // split-K slice offsets
    A += (size_t)blockIdx.z * kChunk;
    B += (size_t)blockIdx.z * kChunk;
    C += (size_t)blockIdx.z * M * N;

    int wm = wrp & 1, wn = wrp >> 1;

    float c[4][4][4];
#pragma unroll
    for (int mi = 0; mi < 4; mi++)
#pragma unroll
        for (int ni = 0; ni < 4; ni++)
#pragma unroll
            for (int r = 0; r < 4; r++) c[mi][ni][r] = 0.f;

    // Load one ktile (A+B) into stage s at k-offset koff.
    auto load_tiles = [&](int s, int koff) {
#pragma unroll
        for (int i = 0; i < 4; i++) {
            int cc = wrp + 8 * i;
            int ks = cc >> 3;
            int kk = ks * 8 + tg + koff;
            uint32_t soff = (uint32_t)(cc << 7) + (uint32_t)(lane << 2);
            {
                int wmc = (cc >> 2) & 1, mi = cc & 3;
                int row = bm + wmc * 64 + mi * 16 + gp;
                const float* p = A + (size_t)row * lda + kk;
                bool ok0 = row < M, ok1 = (row + 8) < M;
                float x0 = ok0 ? p[0] : 0.f;
                float x1 = ok1 ? p[(size_t)8 * lda] : 0.f;
                float x2 = ok0 ? p[4] : 0.f;
                float x3 = ok1 ? p[(size_t)8 * lda + 4] : 0.f;
                uint4 u;
                u.x = f2tf32(x0); u.y = f2tf32(x1); u.z = f2tf32(x2); u.w = f2tf32(x3);
                *(uint4*)&dynsm[s * 8192 + soff] = u;
            }
            {
                int wnc = (cc & 7) >> 1, h = cc & 1;
                int col = bn + wnc * 32 + h * 16 + gp;
                const float* p = B + (size_t)col * ldb + kk;
                bool ok0 = col < N, ok1 = (col + 8) < N;
                float x0 = ok0 ? p[0] : 0.f;
                float x1 = ok0 ? p[4] : 0.f;
                float x2 = ok1 ? p[(size_t)8 * ldb] : 0.f;
                float x3 = ok1 ? p[(size_t)8 * ldb + 4] : 0.f;
                uint4 u;
                u.x = f2tf32(x0); u.y = f2tf32(x1); u.z = f2tf32(x2); u.w = f2tf32(x3);
                *(uint4*)&dynsm[s * 8192 + 4096 + soff] = u;
            }
        }
    };

    auto compute = [&](int s, int ks) {
        const uint32_t* smA = dynsm + s * 8192;
        const uint32_t* smB = smA + 4096;
        uint4 av[4];
#pragma unroll
        for (int mi = 0; mi < 4; mi++)
            av[mi] = *(const uint4*)&smA[((ks * 8 + wm * 4 + mi) << 7) + (lane << 2)];
        uint4 bv0 = *(const uint4*)&smB[((ks * 8 + wn * 2 + 0) << 7) + (lane << 2)];
        uint4 bv1 = *(const uint4*)&smB[((ks * 8 + wn * 2 + 1) << 7) + (lane << 2)];
        uint32_t bf[4][2] = {{bv0.x, bv0.y}, {bv0.z, bv0.w}, {bv1.x, bv1.y}, {bv1.z, bv1.w}};
#pragma unroll
        for (int mi = 0; mi < 4; mi++)
#pragma unroll
            for (int ni = 0; ni < 4; ni++) {
                asm volatile(
                    "mma.sync.aligned.m16n8k8.row.col.f32.tf32.tf32.f32 "
                    "{%0,%1,%2,%3}, {%4,%5,%6,%7}, {%8,%9}, {%0,%1,%2,%3};"
                    : "+f"(c[mi][ni][0]), "+f"(c[mi][ni][1]),
                      "+f"(c[mi][ni][2]), "+f"(c[mi][ni][3])
                    : "r"(av[mi].x), "r"(av[mi].y), "r"(av[mi].z), "r"(av[mi].w),
                      "r"(bf[ni][0]), "r"(bf[ni][1]));
            }
    };

    int nk = kChunk / BK;

    load_tiles(0, 0);
    __syncthreads();

    int s = 0;
    for (int kt = 0; kt < nk; kt++) {
        compute(s, 0);
        compute(s, 1);
        compute(s, 2);
        compute(s, 3);
        if (kt + 1 < nk) load_tiles(s ^ 1, (kt + 1) * BK);
        __syncthreads();
        s ^= 1;
    }

    // --- epilogue ---
#pragma unroll
    for (int mi = 0; mi < 4; mi++) {
        int r0 = bm + wm * 64 + mi * 16 + gp;
#pragma unroll
        for (int ni = 0; ni < 4; ni++) {
            int col = bn + wn * 32 + ni * 8 + 2 * tg;
            if (col >= N) continue;
            float b0 = bias ? bias[col] : 0.f;
            float b1 = bias ? bias[col + 1] : 0.f;
            if (r0 < M) {
                float v0 = c[mi][ni][0] + b0;
                float v1 = c[mi][ni][1] + b1;
                if (relu) { v0 = fmaxf(v0, 0.f); v1 = fmaxf(v1, 0.f); }
                *(float2*)(C + (size_t)r0 * N + col) = make_float2(v0, v1);
            }
            if (r0 + 8 < M) {
                float v2 = c[mi][ni][2] + b0;
                float v3 = c[mi][ni][3] + b1;
                if (relu) { v2 = fmaxf(v2, 0.f); v3 = fmaxf(v3, 0.f); }
                *(float2*)(C + (size_t)(r0 + 8) * N + col) = make_float2(v2, v3);
            }
        }
    }
}

// split-K reduce: out[i] = sum_s part[s*MN+i] (+ bias[i%N]); fixed order => deterministic
__global__ void splitk_reduce(const float* __restrict__ part, const float* __restrict__ bias,
                              float* __restrict__ out, int MN, int N, int S)
{
    int i = blockIdx.x * 256 + threadIdx.x;
    if (i >= MN) return;
    float acc = bias ? bias[i % N] : 0.f;
    for (int si = 0; si < S; si++) acc += part[(size_t)si * MN + i];
    out[i] = acc;
}

// ------------------------- IoU relation mask --------------------------------
__global__ void iou_mask_kernel(const float* __restrict__ bboxes,
                                const float* __restrict__ mask)
{
    int idx = blockIdx.x * blockDim.x + threadIdx.x;
    if (idx >= NB * NRQ * NRQ) return;
    int j = idx % NRQ;
    int i = (idx / NRQ) % NRQ;
    int n = idx / (NRQ * NRQ);
    const float* bi = bboxes + (size_t)(n * NRQ + i) * 4;
    const float* bj = bboxes + (size_t)(n * NRQ + j) * 4;
    float ax0 = bi[0], ay0 = bi[1], ax1 = bi[2], ay1 = bi[3];
    float bx0 = bj[0], by0 = bj[1], bx1 = bj[2], by1 = bj[3];
    float areaA = (ax1 - ax0) * (ay1 - ay0);
    float areaB = (bx1 - bx0) * (by1 - by0);
    float lx = fmaxf(ax0, bx0), ly = fmaxf(ay0, by0);
    float rx = fminf(ax1, bx1), ry = fminf(ay1, by1);
    float w = fmaxf(rx - lx, 0.f), h = fmaxf(ry - ly, 0.f);
    float inter = w * h;
    float uni = areaA + areaB - inter;
    float iou = inter / fmaxf(uni, 1e-9f);
    float mi = mask[n * NRQ + i], mj = mask[n * NRQ + j];
    bool masked = ((iou < 0.5f) && mi > 0.f && mj > 0.f) || (i == j && mi == 0.f);
    g_mflag[idx] = masked ? 1.f : 0.f;
}

// ------------------------- qk = pro + query ---------------------------------
__global__ void qkadd_kernel(const float* __restrict__ pro, const float* __restrict__ query)
{
    int idx = blockIdx.x * blockDim.x + threadIdx.x;
    if (idx >= ROWS * DIM) return;
    g_qk[idx] = pro[idx] + query[idx];
}

// ------------------------- attention scores ---------------------------------
__global__ void scores_kernel()
{
    int n = blockIdx.z, h = blockIdx.y, qt = blockIdx.x * 32;
    __shared__ float Qs[32][32];
    __shared__ float Ks[32][33];
    int tid = threadIdx.x;
    int r = tid / 32, c = tid % 32;
    for (int rr = r; rr < 32; rr += 8) {
        int q = qt + rr;
        Qs[rr][c] = (q < NRQ) ? g_qkp[(size_t)(n * NRQ + q) * 512 + h * 32 + c] : 0.f;
    }
    const float scale = 0.17677669529663687f;  // 1/sqrt(32)
    for (int kt = 0; kt < NRQ; kt += 32) {
        __syncthreads();
        for (int rr = r; rr < 32; rr += 8) {
            int k = kt + rr;
            Ks[rr][c] = (k < NRQ) ? g_qkp[(size_t)(n * NRQ + k) * 512 + 256 + h * 32 + c] : 0.f;
        }
        __syncthreads();
        int kk = tid % 32, qr0 = tid / 32;
        float acc[4] = {0.f, 0.f, 0.f, 0.f};
#pragma unroll
        for (int d = 0; d < 32; d++) {
            float kv = Ks[kk][d];
#pragma unroll
            for (int u = 0; u < 4; u++) acc[u] += Qs[qr0 + u * 8][d] * kv;
        }
#pragma unroll
        for (int u = 0; u < 4; u++) {
            int q = qt + qr0 + u * 8;
            int k = kt + kk;
            if (q < NRQ && k < NRQ) {
                float flag = g_mflag[(size_t)(n * NRQ + q) * NRQ + k];
                size_t off = ((size_t)(n * NHD + h) * NRQ + q) * NRQ + k;
                g_scores[off] = (flag > 0.f) ? -1e9f : acc[u] * scale;
            }
        }
    }
}

// ------------------------- row softmax (one warp per row) -------------------
__global__ void softmax_kernel()
{
    int row = blockIdx.x * 8 + threadIdx.x / 32;
    int lane = threadIdx.x % 32;
    if (row >= NB * NHD * NRQ) return;
    float* p = g_scores + (size_t)row * NRQ;
    float mx = -1e30f;
    for (int k = lane; k < NRQ; k += 32) mx = fmaxf(mx, p[k]);
    for (int o = 16; o; o >>= 1) mx = fmaxf(mx, __shfl_xor_sync(0xffffffffu, mx, o));
    float sum = 0.f;
    for (int k = lane; k < NRQ; k += 32) { float e = __expf(p[k] - mx); p[k] = e; sum += e; }
    for (int o = 16; o; o >>= 1) sum += __shfl_xor_sync(0xffffffffu, sum, o);
    float inv = 1.f / sum;
    for (int k = lane; k < NRQ; k += 32) p[k] *= inv;
}

// ------------------------- ctx = attn @ V -----------------------------------
__global__ void ctx_kernel()
{
    int idx = blockIdx.x * blockDim.x + threadIdx.x;
    if (idx >= ROWS * DIM) return;
    int col = idx & 255;
    int row = idx >> 8;             // n*NRQ + q
    int n = row / NRQ, q = row % NRQ;
    int h = col >> 5;
    const float* ap = g_scores + ((size_t)(n * NHD + h) * NRQ + q) * NRQ;
    float acc = 0.f;
    for (int k = 0; k < NRQ; k++)
        acc += ap[k] * g_vp[(size_t)(n * NRQ + k) * DIM + col];
    g_ctx[idx] = acc;
}

// ------------------------- LayerNorm rows of 256 ----------------------------
__global__ void ln_kernel(const float* __restrict__ x, const float* __restrict__ res,
                          const float* __restrict__ mask, float* __restrict__ out, int relu)
{
    int row = blockIdx.x;
    int c = threadIdx.x;
    size_t base = (size_t)row * DIM;
    float v = x[base + c];
    if (res) v += res[base + c];
    float s = v, q = v * v;
    for (int o = 16; o; o >>= 1) {
        s += __shfl_xor_sync(0xffffffffu, s, o);
        q += __shfl_xor_sync(0xffffffffu, q, o);
    }
    __shared__ float ss[8], sq[8];
    int w = c >> 5, lane = c & 31;
    if (lane == 0) { ss[w] = s; sq[w] = q; }
    __syncthreads();
    float tot = 0.f, totq = 0.f;
#pragma unroll
    for (int i = 0; i < 8; i++) { tot += ss[i]; totq += sq[i]; }
    float mean = tot * (1.f / DIM);
    float var = totq * (1.f / DIM) - mean * mean;
    float y = (v - mean) * rsqrtf(var + 1e-5f);
    if (relu) y = fmaxf(y, 0.f);
    if (mask) y *= mask[row];
    out[base + c] = y;
}

// ------------------------- DynamicConv per instance (v3) ---------------------
// smem cut to ~93 KB -> 2 CTAs/SM. p1/p2 staged in 32 KB halves (contiguous
// copies); summation order over d (f1) and e (f2) preserved -> bit-identical.
// f2 accumulators held in registers across the two p2 halves.
#define DC_SMEM ((SS * DIM + 8192 + SS * DDI) * 4)   // 12544 + 8192 + 3136 floats = 95488 B

__global__ __launch_bounds__(256, 2) void dynconv_kernel(const float* __restrict__ roi)
{
    extern __shared__ float sm[];
    float* fsm  = sm;                     // 12544: feats, later f2 raw
    float* psm  = sm + SS * DIM;          // 8192: half of p1 / p2
    float* f1sm = psm + 8192;             // 3136
    int n = blockIdx.x, tid = threadIdx.x;

    // stage feats (vectorized float4)
    for (int i = tid; i < SS * DIM / 4; i += 256) {
        int s = i >> 6, d4 = i & 63;
        *(float4*)&fsm[s * DIM + d4 * 4] =
            *(const float4*)&roi[((size_t)s * ROWS + n) * DIM + d4 * 4];
    }
    const float* pr = g_params + (size_t)n * (2 * DIM * DDI);

    // ---- f1[s][e] = sum_d feats[s][d] * p1[d][e], two d-halves ----
    int eg = tid & 15, sg = tid >> 4;
    int e0 = eg * 4, s0 = sg * 4;
    float acc1[4][4];
#pragma unroll
    for (int i = 0; i < 4; i++)
#pragma unroll
        for (int j = 0; j < 4; j++) acc1[i][j] = 0.f;
    int srow[4];
#pragma unroll
    for (int i = 0; i < 4; i++)
        srow[i] = ((s0 + i < SS) ? (s0 + i) : (SS - 1)) * DIM;

#pragma unroll
    for (int half = 0; half < 2; half++) {
        __syncthreads();   // feats staged (half 0) / psm readers done (half 1)
        for (int i = tid; i < 2048; i += 256)
            *(float4*)&psm[i * 4] = *(const float4*)&pr[half * 8192 + i * 4];
        __syncthreads();
        if (s0 < SS) {
            int dbase = half * 128;
            for (int d = 0; d < 128; d += 4) {
                float fa[4][4];
#pragma unroll
                for (int i = 0; i < 4; i++) {
                    float4 f4 = *(const float4*)&fsm[srow[i] + dbase + d];
                    fa[i][0] = f4.x; fa[i][1] = f4.y; fa[i][2] = f4.z; fa[i][3] = f4.w;
                }
#pragma unroll
                for (int dd = 0; dd < 4; dd++) {
                    float4 p = *(const float4*)&psm[(d + dd) * DDI + e0];
                    float pa[4] = {p.x, p.y, p.z, p.w};
#pragma unroll
                    for (int i = 0; i < 4; i++)
#pragma unroll
                        for (int j = 0; j < 4; j++)
                            acc1[i][j] = fmaf(fa[i][dd], pa[j], acc1[i][j]);
                }
            }
        }
    }
    if (s0 < SS) {
#pragma unroll
        for (int i = 0; i < 4; i++) {
            if (s0 + i < SS) {
#pragma unroll
                for (int j = 0; j < 4; j++)
                    f1sm[(s0 + i) * DDI + e0 + j] = acc1[i][j];
            }
        }
    }
    __syncthreads();

    // ---- ln over 64 + relu (one warp per row, in-place) ----
    int wid = tid >> 5, lane = tid & 31;
    for (int s = wid; s < SS; s += 8) {
        float a = f1sm[s * DDI + lane], b = f1sm[s * DDI + 32 + lane];
        float sum = a + b, ssq = a * a + b * b;
        for (int o = 16; o; o >>= 1) {
            sum += __shfl_xor_sync(0xffffffffu, sum, o);
            ssq += __shfl_xor_sync(0xffffffffu, ssq, o);
        }
        float mean = sum * (1.f / 64.f);
        float var = ssq * (1.f / 64.f) - mean * mean;
        float inv = rsqrtf(var + 1e-5f);
        f1sm[s * DDI + lane]      = fmaxf((a - mean) * inv, 0.f);
        f1sm[s * DDI + 32 + lane] = fmaxf((b - mean) * inv, 0.f);
    }
    __syncthreads();   // LN done before f2 reads f1sm; also before psm reload

    // ---- f2[s][d] = sum_e f1[s][e] * p2[e][d], two e-halves, accs in regs ----
    int dg = tid & 63, so = tid >> 6;
    int d0 = dg * 4;
    float acc2[4][4][4];   // [t][i][j], sb = so*4 + t*16
#pragma unroll
    for (int t = 0; t < 4; t++)
#pragma unroll
        for (int i = 0; i < 4; i++)
#pragma unroll
            for (int j = 0; j < 4; j++) acc2[t][i][j] = 0.f;

#pragma unroll
    for (int half = 0; half < 2; half++) {
        if (half) __syncthreads();   // protect psm from half-0 readers
        for (int i = tid; i < 2048; i += 256)
            *(float4*)&psm[i * 4] = *(const float4*)&pr[DIM * DDI + half * 8192 + i * 4];
        __syncthreads();
#pragma unroll
        for (int t = 0; t < 4; t++) {
            int sb = so * 4 + t * 16;
            if (sb >= SS) continue;
            int srow2[4];
#pragma unroll
            for (int i = 0; i < 4; i++)
                srow2[i] = ((sb + i < SS) ? (sb + i) : (SS - 1)) * DDI;
            int ebase = half * 32;
            for (int e = 0; e < 32; e += 4) {
                float fa[4][4];
#pragma unroll
                for (int i = 0; i < 4; i++) {
                    float4 f4 = *(const float4*)&f1sm[srow2[i] + ebase + e];
                    fa[i][0] = f4.x; fa[i][1] = f4.y; fa[i][2] = f4.z; fa[i][3] = f4.w;
                }
#pragma unroll
                for (int ee = 0; ee < 4; ee++) {
                    float4 p = *(const float4*)&psm[(e + ee) * DIM + d0];
                    float pa[4] = {p.x, p.y, p.z, p.w};
#pragma unroll
                    for (int i = 0; i < 4; i++)
#pragma unroll
                        for (int j = 0; j < 4; j++)
                            acc2[t][i][j] = fmaf(fa[i][ee], pa[j], acc2[t][i][j]);
                }
            }
        }
    }
    __syncthreads();   // all reads of psm/f1sm complete before fsm reuse is fine (fsm dead)

    // write f2 raw into fsm (feats buffer is dead)
#pragma unroll
    for (int t = 0; t < 4; t++) {
        int sb = so * 4 + t * 16;
        if (sb >= SS) continue;
#pragma unroll
        for (int i = 0; i < 4; i++) {
            if (sb + i < SS) {
#pragma unroll
                for (int j = 0; j < 4; j++)
                    fsm[(sb + i) * DIM + d0 + j] = acc2[t][i][j];
            }
        }
    }
    __syncthreads();

    // ---- ln over 256 + relu, write to g_f2 ----
    for (int s = wid; s < SS; s += 8) {
        float vals[8];
        float sum = 0.f, ssq = 0.f;
#pragma unroll
        for (int u = 0; u < 8; u++) {
            float v = fsm[s * DIM + lane + u * 32];
            vals[u] = v; sum += v; ssq += v * v;
        }
        for (int o = 16; o; o >>= 1) {
            sum += __shfl_xor_sync(0xffffffffu, sum, o);
            ssq += __shfl_xor_sync(0xffffffffu, ssq, o);
        }
        float mean = sum * (1.f / DIM);
        float var = ssq * (1.f / DIM) - mean * mean;
        float inv = rsqrtf(var + 1e-5f);
#pragma unroll
        for (int u = 0; u < 8; u++) {
            float y = fmaxf((vals[u] - mean) * inv, 0.f);
            g_f2[(size_t)n * (SS * DIM) + s * DIM + lane + u * 32] = y;
        }
    }
}

// ------------------------- host launch --------------------------------------
template <typename T>
static float* sym(T& s) { void* p = nullptr; cudaGetSymbolAddress(&p, s); return (float*)p; }

#define GEMM_SMEM 65536

static void launch_gemm(const float* A, const float* B, const float* bias, float* C,
                        int M, int N, int K, int lda, int ldb, int relu, int splitS)
{
    static bool attr_set = false;
    if (!attr_set) {
        cudaFuncSetAttribute(gemm_tf32, cudaFuncAttributeMaxDynamicSharedMemorySize, GEMM_SMEM);
        attr_set = true;
    }
    dim3 g(cdiv(N, BN), cdiv(M, BM), splitS);
    gemm_tf32<<<g, 256, GEMM_SMEM>>>(A, B, bias, C, M, N, K / splitS, lda, ldb, relu);
}

extern "C" void kernel_launch(void* const* d_in, const int* in_sizes, int n_in,
                              void* d_out, int out_size)
{
    const float* bboxes   = (const float*)d_in[0];
    const float* pro      = (const float*)d_in[1];
    const float* roi      = (const float*)d_in[2];
    const float* query    = (const float*)d_in[3];
    const float* mask     = (const float*)d_in[4];
    const float* w_qkv    = (const float*)d_in[5];
    const float* b_qkv    = (const float*)d_in[6];
    const float* w_attn   = (const float*)d_in[7];
    const float* b_attn   = (const float*)d_in[8];
    const float* w_dyn    = (const float*)d_in[9];
    const float* b_dyn    = (const float*)d_in[10];
    const float* w_dyno   = (const float*)d_in[11];
    const float* b_dyno   = (const float*)d_in[12];
    const float* w_ff1    = (const float*)d_in[13];
    const float* b_ff1    = (const float*)d_in[14];
    const float* w_ff2    = (const float*)d_in[15];
    const float* b_ff2    = (const float*)d_in[16];
    const float* w_cls    = (const float*)d_in[17];
    const float* w_logits = (const float*)d_in[18];
    const float* b_logits = (const float*)d_in[19];
    float* out = (float*)d_out;

    float* p_qk    = sym(g_qk);
    float* p_qkp   = sym(g_qkp);
    float* p_vp    = sym(g_vp);
    float* p_ctx   = sym(g_ctx);
    float* p_tgt2  = sym(g_tgt2);
    float* p_pf1   = sym(g_pf1);
    float* p_params= sym(g_params);
    float* p_f2    = sym(g_f2);
    float* p_dynr  = sym(g_dynraw);
    float* p_pf2   = sym(g_pf2);
    float* p_pfB   = sym(g_pfB);
    float* p_ffh   = sym(g_ffh);
    float* p_t2    = sym(g_t2);
    float* p_fc    = sym(g_fc);
    float* p_g1    = sym(g_g1);
    float* p_clsf  = sym(g_clsf);

    // 1. IoU relation mask
    iou_mask_kernel<<<cdiv(NB * NRQ * NRQ, 256), 256>>>(bboxes, mask);
    // 2. qk = pro + query
    qkadd_kernel<<<cdiv(ROWS * DIM, 256), 256>>>(pro, query);
    // 3. q,k projection: [2400,512], split-K=2 (g_params free -> scratch)
    launch_gemm(p_qk, w_qkv, nullptr, p_params, ROWS, 512, DIM, DIM, DIM, 0, 2);
    splitk_reduce<<<cdiv(ROWS * 512, 256), 256>>>(p_params, b_qkv, p_qkp, ROWS * 512, 512, 2);
    // 4. v projection from pro_features, split-K=2 (use scratch past QK partials)
    {
        float* scr = p_params + 2 * ROWS * 512;
        launch_gemm(pro, w_qkv + 512 * DIM, nullptr, scr, ROWS, DIM, DIM, DIM, DIM, 0, 2);
        splitk_reduce<<<cdiv(ROWS * DIM, 256), 256>>>(scr, b_qkv + 512, p_vp, ROWS * DIM, DIM, 2);
    }
    // 5-7. attention
    {
        dim3 g(cdiv(NRQ, 32), NHD, NB);
        scores_kernel<<<g, 256>>>();
    }
    softmax_kernel<<<cdiv(NB * NHD * NRQ, 8), 256>>>();
    ctx_kernel<<<cdiv(ROWS * DIM, 256), 256>>>();
    // 8. out proj, split-K=2
    launch_gemm(p_ctx, w_attn, nullptr, p_params, ROWS, DIM, DIM, DIM, DIM, 0, 2);
    splitk_reduce<<<cdiv(ROWS * DIM, 256), 256>>>(p_params, b_attn, p_tgt2, ROWS * DIM, DIM, 2);
    // 9. norm1 + mask
    ln_kernel<<<ROWS, 256>>>(p_tgt2, pro, mask, p_pf1, 0);
    // 10. dyn params GEMM [2400, 32768] (full grid already)
    launch_gemm(p_pf1, w_dyn, b_dyn, p_params, ROWS, 2 * DIM * DDI, DIM, DIM, DIM, 0, 1);
    // 11. per-instance dynamic conv (2 CTAs/SM)
    {
        cudaFuncSetAttribute(dynconv_kernel, cudaFuncAttributeMaxDynamicSharedMemorySize, DC_SMEM);
        dynconv_kernel<<<ROWS, 256, DC_SMEM>>>(roi);
    }
    // 12. out_layer GEMM: [2400,256], K=12544, split-K=8 (g_params free -> scratch)
    launch_gemm(p_f2, w_dyno, nullptr, p_params, ROWS, DIM, SS * DIM, SS * DIM, SS * DIM, 0, 8);
    splitk_reduce<<<cdiv(ROWS * DIM, 256), 256>>>(p_params, b_dyno, p_dynr, ROWS * DIM, DIM, 8);
    // 13. pf2 = relu(ln(dynraw))
    ln_kernel<<<ROWS, 256>>>(p_dynr, nullptr, nullptr, p_pf2, 1);
    // 14. norm2: pfB = ln(pf1 + pf2)
    ln_kernel<<<ROWS, 256>>>(p_pf2, p_pf1, nullptr, p_pfB, 0);
    // 15. FFN 1 (relu)
    launch_gemm(p_pfB, w_ff1, b_ff1, p_ffh, ROWS, FFD, DIM, DIM, DIM, 1, 1);
    // 16. FFN 2, split-K=4
    launch_gemm(p_ffh, w_ff2, nullptr, p_params, ROWS, DIM, FFD, FFD, FFD, 0, 4);
    splitk_reduce<<<cdiv(ROWS * DIM, 256), 256>>>(p_params, b_ff2, p_t2, ROWS * DIM, DIM, 4);
    // 17. norm3 + mask -> fc
    ln_kernel<<<ROWS, 256>>>(p_t2, p_pfB, mask, p_fc, 0);
    // 18. cls tower linear (no bias), split-K=2
    launch_gemm(p_fc, w_cls, nullptr, p_params, ROWS, DIM, DIM, DIM, DIM, 0, 2);
    splitk_reduce<<<cdiv(ROWS * DIM, 256), 256>>>(p_params, nullptr, p_g1, ROWS * DIM, DIM, 2);
    // 19. cls_f = relu(ln(g1))
    ln_kernel<<<ROWS, 256>>>(p_g1, nullptr, nullptr, p_clsf, 1);
    // 20. logits -> d_out [2400, 80], split-K=2
    launch_gemm(p_clsf, w_logits, nullptr, p_params, ROWS, NCLS, DIM, DIM, DIM, 0, 2);
    splitk_reduce<<<cdiv(ROWS * NCLS, 256), 256>>>(p_params, b_logits, out, ROWS * NCLS, NCLS, 2);
}